// round 1
// baseline (speedup 1.0000x reference)
#include <cuda_runtime.h>
#include <cstdint>

// Problem constants (fixed by the reference)
#define NNODES 50000
#define INC    256
#define HC     128
#define OUTC   64

// ---------------- scratch (static __device__ — no allocations) ----------------
__device__ float g_H1[NNODES * 2 * HC];   // seq@W1          [N,256]
__device__ float g_A1[NNODES * 2 * HC];   // agg1 / x1       [N,256]
__device__ float g_H2[NNODES * HC];       // x1@W2           [N,128]
__device__ float g_A2[NNODES * HC];       // agg2            [N,128]
__device__ float g_T1[2 * HC * HC];       // Wfc2@Wfc3_top   [256,128]
__device__ float g_T2[HC * HC];           // Wfc1@Wfc3_bot   [128,128]
__device__ float g_PA[2 * HC * OUTC];     // T1@Wfc4         [256,64]
__device__ float g_PB[HC * OUTC];         // T2@Wfc4         [128,64]
__device__ float g_F[NNODES * OUTC];      // seq@PA          [N,64]

// ---------------- generic fp32 tiled GEMM ----------------
// D = A[M,K] @ B[K,N]  (+ Cin) (+ bias) (then PReLU(alpha))
// Requires: K % 16 == 0, N % 64 == 0. M arbitrary.
#define BM 64
#define BN 64
#define BK 16

__global__ void gemm_k(const float* __restrict__ A, const float* __restrict__ B,
                       const float* __restrict__ Cin, float* __restrict__ D,
                       int M, int K, int N,
                       const float* __restrict__ alpha,
                       const float* __restrict__ bias)
{
    __shared__ float As[BK][BM];
    __shared__ float Bs[BK][BN];
    const int bm = blockIdx.y * BM, bn = blockIdx.x * BN;
    const int tid = threadIdx.x;
    const int tx = tid & 15, ty = tid >> 4;   // 16x16 thread grid, 4x4 per thread
    float acc[4][4] = {};

    for (int k0 = 0; k0 < K; k0 += BK) {
        #pragma unroll
        for (int i = 0; i < 4; i++) {
            int idx = tid + i * 256;          // 0..1023
            int r = idx >> 4, kk = idx & 15;
            int row = bm + r;
            As[kk][r] = (row < M) ? A[(size_t)row * K + k0 + kk] : 0.f;
        }
        #pragma unroll
        for (int i = 0; i < 4; i++) {
            int idx = tid + i * 256;
            int kk = idx >> 6, c = idx & 63;
            Bs[kk][c] = B[(size_t)(k0 + kk) * N + bn + c];
        }
        __syncthreads();
        #pragma unroll
        for (int kk = 0; kk < BK; kk++) {
            float4 av = *reinterpret_cast<const float4*>(&As[kk][ty * 4]);
            float4 bv = *reinterpret_cast<const float4*>(&Bs[kk][tx * 4]);
            float a[4] = {av.x, av.y, av.z, av.w};
            float b[4] = {bv.x, bv.y, bv.z, bv.w};
            #pragma unroll
            for (int i = 0; i < 4; i++)
                #pragma unroll
                for (int j = 0; j < 4; j++)
                    acc[i][j] += a[i] * b[j];
        }
        __syncthreads();
    }

    const float al = alpha ? alpha[0] : 0.f;
    #pragma unroll
    for (int i = 0; i < 4; i++) {
        int r = bm + ty * 4 + i;
        if (r >= M) return;
        #pragma unroll
        for (int j = 0; j < 4; j++) {
            int c = bn + tx * 4 + j;
            float v = acc[i][j];
            if (bias) v += bias[c];
            if (Cin)  v += Cin[(size_t)r * N + c];
            if (alpha) v = (v >= 0.f) ? v : al * v;
            D[(size_t)r * N + c] = v;
        }
    }
}

// ---------------- edge scatter: agg[dst] += ew * h[src], one warp per edge ----------------
template<int C>
__global__ void scatter_k(const float* __restrict__ h, const int* __restrict__ src,
                          const int* __restrict__ dst, const float* __restrict__ ew,
                          float* __restrict__ agg, int E)
{
    int gw = blockIdx.x * (blockDim.x >> 5) + (threadIdx.x >> 5);
    int lane = threadIdx.x & 31;
    if (gw >= E) return;
    int s = __ldg(src + gw);
    int d = __ldg(dst + gw);
    float w = __ldg(ew + gw);
    const float4* hr = reinterpret_cast<const float4*>(h + (size_t)s * C);
    float* ar = agg + (size_t)d * C;
    #pragma unroll
    for (int i = 0; i < C / 128; i++) {
        float4 v = __ldg(hr + lane + i * 32);
        int c = (lane + i * 32) * 4;
        atomicAdd(ar + c + 0, w * v.x);
        atomicAdd(ar + c + 1, w * v.y);
        atomicAdd(ar + c + 2, w * v.z);
        atomicAdd(ar + c + 3, w * v.w);
    }
}

// ---------------- elementwise helpers (float4 vectorized) ----------------
__global__ void binit4_k(float4* __restrict__ agg, const float4* __restrict__ b,
                         int total4, int c4mask)
{
    int i = blockIdx.x * blockDim.x + threadIdx.x;
    if (i < total4) agg[i] = b[i & c4mask];
}

__global__ void prelu4_k(const float4* __restrict__ in, float4* __restrict__ out,
                         int n4, const float* __restrict__ a)
{
    int i = blockIdx.x * blockDim.x + threadIdx.x;
    if (i < n4) {
        float al = a[0];
        float4 v = in[i];
        v.x = (v.x >= 0.f) ? v.x : al * v.x;
        v.y = (v.y >= 0.f) ? v.y : al * v.y;
        v.z = (v.z >= 0.f) ? v.z : al * v.z;
        v.w = (v.w >= 0.f) ? v.w : al * v.w;
        out[i] = v;
    }
}

// ---------------- launch ----------------
extern "C" void kernel_launch(void* const* d_in, const int* in_sizes, int n_in,
                              void* d_out, int out_size)
{
    const float* seq  = (const float*)d_in[0];
    const int*   ei   = (const int*)  d_in[1];
    const float* ew   = (const float*)d_in[2];
    const float* W1   = (const float*)d_in[3];
    const float* b1   = (const float*)d_in[4];
    const float* W2   = (const float*)d_in[5];
    const float* b2   = (const float*)d_in[6];
    const float* a1   = (const float*)d_in[7];
    const float* a2   = (const float*)d_in[8];
    const float* a3   = (const float*)d_in[9];
    const float* Wfc1 = (const float*)d_in[10];
    const float* Wfc2 = (const float*)d_in[11];
    const float* Wfc3 = (const float*)d_in[12];
    const float* Wfc4 = (const float*)d_in[13];

    const int N = in_sizes[0] / INC;     // 50000
    const int E = in_sizes[2];           // 800000
    const int* src = ei;
    const int* dst = ei + E;

    float *H1, *A1, *H2, *A2, *T1, *T2, *PA, *PB, *F;
    cudaGetSymbolAddress((void**)&H1, g_H1);
    cudaGetSymbolAddress((void**)&A1, g_A1);
    cudaGetSymbolAddress((void**)&H2, g_H2);
    cudaGetSymbolAddress((void**)&A2, g_A2);
    cudaGetSymbolAddress((void**)&T1, g_T1);
    cudaGetSymbolAddress((void**)&T2, g_T2);
    cudaGetSymbolAddress((void**)&PA, g_PA);
    cudaGetSymbolAddress((void**)&PB, g_PB);
    cudaGetSymbolAddress((void**)&F,  g_F);

    float* outx = (float*)d_out;                      // x:     [N,128]
    float* outf = (float*)d_out + (size_t)N * HC;     // feat1: [N,64]

    const dim3 blk(256);
    const int gy = (N + BM - 1) / BM;                 // 782

    // ---- fold the FC head: PA = Wfc2@Wfc3[:256]@Wfc4, PB = Wfc1@Wfc3[256:]@Wfc4 ----
    gemm_k<<<dim3(2, 4), blk>>>(Wfc2, Wfc3,                nullptr, T1, 2*HC, 2*HC, HC,   nullptr, nullptr);
    gemm_k<<<dim3(2, 2), blk>>>(Wfc1, Wfc3 + 2*HC*HC,      nullptr, T2, HC,   2*HC, HC,   nullptr, nullptr);
    gemm_k<<<dim3(1, 4), blk>>>(T1,   Wfc4,                nullptr, PA, 2*HC, HC,   OUTC, nullptr, nullptr);
    gemm_k<<<dim3(1, 2), blk>>>(T2,   Wfc4,                nullptr, PB, HC,   HC,   OUTC, nullptr, nullptr);

    // ---- GCN layer 1: x1 = prelu(scatter(ew * (seq@W1)[src] -> dst) + b1, a1) ----
    gemm_k<<<dim3(4, gy), blk>>>(seq, W1, nullptr, H1, N, INC, 2*HC, nullptr, nullptr);
    {
        int total4 = N * 2 * HC / 4;
        binit4_k<<<(total4 + 255) / 256, blk>>>((float4*)A1, (const float4*)b1, total4, (2*HC/4) - 1);
    }
    scatter_k<2*HC><<<(E + 7) / 8, blk>>>(H1, src, dst, ew, A1, E);
    {
        int n4 = N * 2 * HC / 4;
        prelu4_k<<<(n4 + 255) / 256, blk>>>((const float4*)A1, (float4*)A1, n4, a1);
    }

    // ---- GCN layer 2: x = prelu(scatter(ew * (x1@W2)[src] -> dst) + b2, a2) ----
    gemm_k<<<dim3(2, gy), blk>>>(A1, W2, nullptr, H2, N, 2*HC, HC, nullptr, nullptr);
    {
        int total4 = N * HC / 4;
        binit4_k<<<(total4 + 255) / 256, blk>>>((float4*)A2, (const float4*)b2, total4, (HC/4) - 1);
    }
    scatter_k<HC><<<(E + 7) / 8, blk>>>(H2, src, dst, ew, A2, E);
    {
        int n4 = N * HC / 4;
        prelu4_k<<<(n4 + 255) / 256, blk>>>((const float4*)A2, (float4*)outx, n4, a2);
    }

    // ---- folded head: feat1 = prelu(seq@PA + x@PB, a3) ----
    gemm_k<<<dim3(1, gy), blk>>>(seq,  PA, nullptr, F,    N, INC, OUTC, nullptr, nullptr);
    gemm_k<<<dim3(1, gy), blk>>>(outx, PB, F,       outf, N, HC,  OUTC, a3,      nullptr);
}

// round 3
// speedup vs baseline: 1.6731x; 1.6731x over previous
#include <cuda_runtime.h>
#include <cstdint>

#define NNODES 50000
#define INC    256
#define HC     128
#define OUTC   64

// ---------------- scratch (static __device__ — no allocations) ----------------
__device__ float g_H1[NNODES * 2 * HC];   // seq@W1          [N,256]
__device__ float g_A1[NNODES * 2 * HC];   // agg1 (pre-act)  [N,256]
__device__ float g_H2[NNODES * HC];       // prelu(A1)@W2    [N,128]
__device__ float g_A2[NNODES * HC];       // agg2            [N,128]
__device__ float g_T1[2 * HC * HC];       // Wfc2@Wfc3_top   [256,128]
__device__ float g_T2[HC * HC];           // Wfc1@Wfc3_bot   [128,128]
__device__ float g_PA[2 * HC * OUTC];     // T1@Wfc4         [256,64]
__device__ float g_PB[HC * OUTC];         // T2@Wfc4         [128,64]
__device__ float g_F[NNODES * OUTC];      // seq@PA          [N,64]

// ---------------- fp32 tiled GEMM, TMxTN per thread ----------------
// D = op(A)[M,K] @ B[K,N] (+ Cin) (then PReLU(alphaOut))
// op(A) = preluA ? prelu(A, preluA) : A  (fused activation on the A operand)
// Requires: K % BK == 0, N % BN == 0. M arbitrary.
template<int BM, int BN, int BK, int TM, int TN>
__global__ void __launch_bounds__(256)
sgemm_k(const float* __restrict__ A, const float* __restrict__ B,
        const float* __restrict__ Cin, float* __restrict__ D,
        int M, int K, int N,
        const float* __restrict__ preluA,
        const float* __restrict__ alphaOut)
{
    constexpr int THREADS = (BM / TM) * (BN / TN);     // 256
    static_assert(THREADS == 256, "block must be 256 threads");
    __shared__ float As[BK][BM];
    __shared__ float Bs[BK][BN];

    const int bm = blockIdx.y * BM, bn = blockIdx.x * BN;
    const int tid = threadIdx.x;
    const int tx = tid % (BN / TN);
    const int ty = tid / (BN / TN);

    float acc[TM][TN] = {};
    const float aA = preluA ? preluA[0] : 0.f;
    const bool doPreluA = (preluA != nullptr);

    for (int k0 = 0; k0 < K; k0 += BK) {
        // ---- load A tile (transposed into As[k][m]) ----
        constexpr int A4 = BM * BK / 4;
        #pragma unroll
        for (int l = 0; l < (A4 + THREADS - 1) / THREADS; l++) {
            int idx = tid + l * THREADS;
            if (A4 % THREADS == 0 || idx < A4) {
                int r  = idx / (BK / 4);
                int kc = (idx % (BK / 4)) * 4;
                float4 v = make_float4(0.f, 0.f, 0.f, 0.f);
                if (bm + r < M)
                    v = *reinterpret_cast<const float4*>(&A[(size_t)(bm + r) * K + k0 + kc]);
                if (doPreluA) {
                    v.x = (v.x >= 0.f) ? v.x : aA * v.x;
                    v.y = (v.y >= 0.f) ? v.y : aA * v.y;
                    v.z = (v.z >= 0.f) ? v.z : aA * v.z;
                    v.w = (v.w >= 0.f) ? v.w : aA * v.w;
                }
                As[kc + 0][r] = v.x;
                As[kc + 1][r] = v.y;
                As[kc + 2][r] = v.z;
                As[kc + 3][r] = v.w;
            }
        }
        // ---- load B tile ----
        constexpr int B4 = BK * BN / 4;
        #pragma unroll
        for (int l = 0; l < (B4 + THREADS - 1) / THREADS; l++) {
            int idx = tid + l * THREADS;
            if (B4 % THREADS == 0 || idx < B4) {
                int kk = idx / (BN / 4);
                int c  = (idx % (BN / 4)) * 4;
                *reinterpret_cast<float4*>(&Bs[kk][c]) =
                    *reinterpret_cast<const float4*>(&B[(size_t)(k0 + kk) * N + bn + c]);
            }
        }
        __syncthreads();

        #pragma unroll
        for (int kk = 0; kk < BK; kk++) {
            float a[TM], b[TN];
            #pragma unroll
            for (int i = 0; i < TM / 4; i++)
                *reinterpret_cast<float4*>(&a[i * 4]) =
                    *reinterpret_cast<const float4*>(&As[kk][ty * TM + i * 4]);
            #pragma unroll
            for (int j = 0; j < TN / 4; j++)
                *reinterpret_cast<float4*>(&b[j * 4]) =
                    *reinterpret_cast<const float4*>(&Bs[kk][tx * TN + j * 4]);
            #pragma unroll
            for (int i = 0; i < TM; i++)
                #pragma unroll
                for (int j = 0; j < TN; j++)
                    acc[i][j] += a[i] * b[j];
        }
        __syncthreads();
    }

    const float al = alphaOut ? alphaOut[0] : 0.f;
    #pragma unroll
    for (int i = 0; i < TM; i++) {
        int r = bm + ty * TM + i;
        if (r >= M) return;
        #pragma unroll
        for (int j = 0; j < TN; j += 4) {
            int c = bn + tx * TN + j;
            float4 v = make_float4(acc[i][j], acc[i][j + 1], acc[i][j + 2], acc[i][j + 3]);
            if (Cin) {
                float4 ci = *reinterpret_cast<const float4*>(&Cin[(size_t)r * N + c]);
                v.x += ci.x; v.y += ci.y; v.z += ci.z; v.w += ci.w;
            }
            if (alphaOut) {
                v.x = (v.x >= 0.f) ? v.x : al * v.x;
                v.y = (v.y >= 0.f) ? v.y : al * v.y;
                v.z = (v.z >= 0.f) ? v.z : al * v.z;
                v.w = (v.w >= 0.f) ? v.w : al * v.w;
            }
            *reinterpret_cast<float4*>(&D[(size_t)r * N + c]) = v;
        }
    }
}

// ---------------- edge scatter: agg[dst] += ew * h[src] ----------------
// One warp per edge; vectorized red.global.add.v4.f32 (sm_90+).
__device__ __forceinline__ void red_add_v4(float* p, float4 v) {
    asm volatile("red.global.add.v4.f32 [%0], {%1, %2, %3, %4};"
                 :: "l"(p), "f"(v.x), "f"(v.y), "f"(v.z), "f"(v.w) : "memory");
}

template<int C>
__global__ void scatter_k(const float* __restrict__ h, const int* __restrict__ src,
                          const int* __restrict__ dst, const float* __restrict__ ew,
                          float* __restrict__ agg, int E)
{
    int gw = blockIdx.x * (blockDim.x >> 5) + (threadIdx.x >> 5);
    int lane = threadIdx.x & 31;
    if (gw >= E) return;
    int s = __ldg(src + gw);
    int d = __ldg(dst + gw);
    float w = __ldg(ew + gw);
    const float4* hr = reinterpret_cast<const float4*>(h + (size_t)s * C);
    float* ar = agg + (size_t)d * C;
    #pragma unroll
    for (int i = 0; i < C / 128; i++) {
        int idx = lane + i * 32;
        float4 v = __ldg(hr + idx);
        v.x *= w; v.y *= w; v.z *= w; v.w *= w;
        red_add_v4(ar + idx * 4, v);
    }
}

// ---------------- elementwise helpers ----------------
__global__ void binit4_k(float4* __restrict__ agg, const float4* __restrict__ b,
                         int total4, int c4mask)
{
    int i = blockIdx.x * blockDim.x + threadIdx.x;
    if (i < total4) agg[i] = b[i & c4mask];
}

__global__ void prelu4_k(const float4* __restrict__ in, float4* __restrict__ out,
                         int n4, const float* __restrict__ a)
{
    int i = blockIdx.x * blockDim.x + threadIdx.x;
    if (i < n4) {
        float al = a[0];
        float4 v = in[i];
        v.x = (v.x >= 0.f) ? v.x : al * v.x;
        v.y = (v.y >= 0.f) ? v.y : al * v.y;
        v.z = (v.z >= 0.f) ? v.z : al * v.z;
        v.w = (v.w >= 0.f) ? v.w : al * v.w;
        out[i] = v;
    }
}

// ---------------- launch ----------------
extern "C" void kernel_launch(void* const* d_in, const int* in_sizes, int n_in,
                              void* d_out, int out_size)
{
    const float* seq  = (const float*)d_in[0];
    const int*   ei   = (const int*)  d_in[1];
    const float* ew   = (const float*)d_in[2];
    const float* W1   = (const float*)d_in[3];
    const float* b1   = (const float*)d_in[4];
    const float* W2   = (const float*)d_in[5];
    const float* b2   = (const float*)d_in[6];
    const float* a1   = (const float*)d_in[7];
    const float* a2   = (const float*)d_in[8];
    const float* a3   = (const float*)d_in[9];
    const float* Wfc1 = (const float*)d_in[10];
    const float* Wfc2 = (const float*)d_in[11];
    const float* Wfc3 = (const float*)d_in[12];
    const float* Wfc4 = (const float*)d_in[13];

    const int N = in_sizes[0] / INC;     // 50000
    const int E = in_sizes[2];           // 800000
    const int* src = ei;
    const int* dst = ei + E;

    float *H1, *A1, *H2, *A2, *T1, *T2, *PA, *PB, *F;
    cudaGetSymbolAddress((void**)&H1, g_H1);
    cudaGetSymbolAddress((void**)&A1, g_A1);
    cudaGetSymbolAddress((void**)&H2, g_H2);
    cudaGetSymbolAddress((void**)&A2, g_A2);
    cudaGetSymbolAddress((void**)&T1, g_T1);
    cudaGetSymbolAddress((void**)&T2, g_T2);
    cudaGetSymbolAddress((void**)&PA, g_PA);
    cudaGetSymbolAddress((void**)&PB, g_PB);
    cudaGetSymbolAddress((void**)&F,  g_F);

    float* outx = (float*)d_out;                      // x:     [N,128]
    float* outf = (float*)d_out + (size_t)N * HC;     // feat1: [N,64]

    const dim3 blk(256);
    const int gy = (N + 127) / 128;                   // 391

    // ---- fold the FC head: PA = Wfc2@Wfc3[:256]@Wfc4, PB = Wfc1@Wfc3[256:]@Wfc4 ----
    sgemm_k<128,128,8,8,8><<<dim3(1, 2), blk>>>(Wfc2, Wfc3,           nullptr, T1, 2*HC, 2*HC, HC,   nullptr, nullptr);
    sgemm_k<128,128,8,8,8><<<dim3(1, 1), blk>>>(Wfc1, Wfc3 + 2*HC*HC, nullptr, T2, HC,   2*HC, HC,   nullptr, nullptr);
    sgemm_k<128, 64,8,8,4><<<dim3(1, 2), blk>>>(T1,   Wfc4,           nullptr, PA, 2*HC, HC,   OUTC, nullptr, nullptr);
    sgemm_k<128, 64,8,8,4><<<dim3(1, 1), blk>>>(T2,   Wfc4,           nullptr, PB, HC,   HC,   OUTC, nullptr, nullptr);

    // ---- GCN layer 1: A1 = scatter(ew * (seq@W1)[src] -> dst) + b1  (prelu deferred) ----
    sgemm_k<128,128,8,8,8><<<dim3(2, gy), blk>>>(seq, W1, nullptr, H1, N, INC, 2*HC, nullptr, nullptr);
    {
        int total4 = N * 2 * HC / 4;
        binit4_k<<<(total4 + 255) / 256, blk>>>((float4*)A1, (const float4*)b1, total4, (2*HC/4) - 1);
    }
    scatter_k<2*HC><<<(E + 7) / 8, blk>>>(H1, src, dst, ew, A1, E);

    // ---- GCN layer 2: H2 = prelu(A1, a1) @ W2  (PReLU fused into A-load) ----
    sgemm_k<128,128,8,8,8><<<dim3(1, gy), blk>>>(A1, W2, nullptr, H2, N, 2*HC, HC, a1, nullptr);
    {
        int total4 = N * HC / 4;
        binit4_k<<<(total4 + 255) / 256, blk>>>((float4*)A2, (const float4*)b2, total4, (HC/4) - 1);
    }
    scatter_k<HC><<<(E + 7) / 8, blk>>>(H2, src, dst, ew, A2, E);
    {
        int n4 = N * HC / 4;
        prelu4_k<<<(n4 + 255) / 256, blk>>>((const float4*)A2, (float4*)outx, n4, a2);
    }

    // ---- folded head: feat1 = prelu(seq@PA + x@PB, a3) ----
    sgemm_k<128,64,8,8,4><<<dim3(1, gy), blk>>>(seq,  PA, nullptr, F,    N, INC, OUTC, nullptr, nullptr);
    sgemm_k<128,64,8,8,4><<<dim3(1, gy), blk>>>(outx, PB, F,       outf, N, HC,  OUTC, nullptr, a3);
}

// round 5
// speedup vs baseline: 1.8091x; 1.0813x over previous
#include <cuda_runtime.h>
#include <cstdint>

#define NNODES 50000
#define INC    256
#define HC     128
#define OUTC   64

// ---------------- scratch (static __device__ — no allocations) ----------------
__device__ float g_H1[NNODES * 2 * HC];   // seq@W1          [N,256]
__device__ float g_A1[NNODES * 2 * HC];   // agg1 (pre-act)  [N,256]
__device__ float g_H2[NNODES * HC];       // prelu(A1)@W2    [N,128]
__device__ float g_A2[NNODES * HC];       // agg2            [N,128]
__device__ float g_U [4 * HC * OUTC];     // Wfc3@Wfc4       [512,64]
__device__ float g_PA[2 * HC * OUTC];     // Wfc2@U_top      [256,64]
__device__ float g_PB[HC * OUTC];         // Wfc1@U_bot      [128,64]

// ---------------- double-buffered fp32 GEMM segment ----------------
// Accumulates acc += op(A)[M,K] @ B[K,N] for this block's tile.
// op(A) = doPrelu ? prelu(A, aA) : A. Requires K % BK == 0, N % BN == 0.
template<int BM, int BN, int BK, int TM, int TN, int THREADS>
__device__ __forceinline__ void gemm_seg(
    const float* __restrict__ A, const float* __restrict__ B,
    int M, int K, int N, int bm, int bn, int tid, int tx, int ty,
    float (&As)[2][BK][BM], float (&Bs)[2][BK][BN],
    float (&acc)[TM][TN], bool doPrelu, float aA)
{
    constexpr int A4 = BM * BK / 4;
    constexpr int B4 = BK * BN / 4;
    constexpr int AL = A4 / THREADS;
    constexpr int BL = B4 / THREADS;
    static_assert(A4 % THREADS == 0 && B4 % THREADS == 0, "tile/thread mismatch");

    float4 aReg[AL], bReg[BL];
    const int nt = K / BK;

    auto loadA = [&](int t) {
        #pragma unroll
        for (int l = 0; l < AL; l++) {
            int idx = tid + l * THREADS;
            int r   = idx / (BK / 4);
            int kc  = (idx % (BK / 4)) * 4;
            int row = bm + r;
            float4 v = make_float4(0.f, 0.f, 0.f, 0.f);
            if (row < M)
                v = *reinterpret_cast<const float4*>(&A[(size_t)row * K + t * BK + kc]);
            aReg[l] = v;
        }
    };
    auto loadB = [&](int t) {
        #pragma unroll
        for (int l = 0; l < BL; l++) {
            int idx = tid + l * THREADS;
            int kk  = idx / (BN / 4);
            int c   = (idx % (BN / 4)) * 4;
            bReg[l] = *reinterpret_cast<const float4*>(&B[(size_t)(t * BK + kk) * N + bn + c]);
        }
    };
    auto storeTiles = [&](int buf) {
        #pragma unroll
        for (int l = 0; l < AL; l++) {
            int idx = tid + l * THREADS;
            int r   = idx / (BK / 4);
            int kc  = (idx % (BK / 4)) * 4;
            float4 v = aReg[l];
            if (doPrelu) {
                v.x = (v.x >= 0.f) ? v.x : aA * v.x;
                v.y = (v.y >= 0.f) ? v.y : aA * v.y;
                v.z = (v.z >= 0.f) ? v.z : aA * v.z;
                v.w = (v.w >= 0.f) ? v.w : aA * v.w;
            }
            As[buf][kc + 0][r] = v.x;
            As[buf][kc + 1][r] = v.y;
            As[buf][kc + 2][r] = v.z;
            As[buf][kc + 3][r] = v.w;
        }
        #pragma unroll
        for (int l = 0; l < BL; l++) {
            int idx = tid + l * THREADS;
            int kk  = idx / (BN / 4);
            int c   = (idx % (BN / 4)) * 4;
            *reinterpret_cast<float4*>(&Bs[buf][kk][c]) = bReg[l];
        }
    };

    loadA(0); loadB(0);
    storeTiles(0);
    __syncthreads();

    int buf = 0;
    for (int t = 0; t < nt; t++) {
        if (t + 1 < nt) { loadA(t + 1); loadB(t + 1); }   // overlap with compute
        #pragma unroll
        for (int kk = 0; kk < BK; kk++) {
            float a[TM], b[TN];
            #pragma unroll
            for (int i = 0; i < TM / 4; i++)
                *reinterpret_cast<float4*>(&a[i * 4]) =
                    *reinterpret_cast<const float4*>(&As[buf][kk][ty * TM + i * 4]);
            #pragma unroll
            for (int j = 0; j < TN / 4; j++)
                *reinterpret_cast<float4*>(&b[j * 4]) =
                    *reinterpret_cast<const float4*>(&Bs[buf][kk][tx * TN + j * 4]);
            #pragma unroll
            for (int i = 0; i < TM; i++)
                #pragma unroll
                for (int j = 0; j < TN; j++)
                    acc[i][j] += a[i] * b[j];
        }
        if (t + 1 < nt) storeTiles(buf ^ 1);
        __syncthreads();
        buf ^= 1;
    }
}

// ---------------- GEMM kernel: D = op(A)@B [+ A2@B2] (then PReLU) ----------------
template<int BM, int BN, int BK, int TM, int TN>
__global__ void __launch_bounds__(256)
sgemm_k(const float* __restrict__ A, const float* __restrict__ B, int K,
        const float* __restrict__ A2, const float* __restrict__ B2, int K2,
        float* __restrict__ D, int M, int N,
        const float* __restrict__ preluA, const float* __restrict__ alphaOut)
{
    constexpr int THREADS = (BM / TM) * (BN / TN);
    static_assert(THREADS == 256, "block must be 256 threads");
    __shared__ float As[2][BK][BM];
    __shared__ float Bs[2][BK][BN];

    const int bm = blockIdx.y * BM, bn = blockIdx.x * BN;
    const int tid = threadIdx.x;
    const int tx = tid % (BN / TN);
    const int ty = tid / (BN / TN);

    float acc[TM][TN] = {};
    const float aA = preluA ? preluA[0] : 0.f;

    gemm_seg<BM, BN, BK, TM, TN, THREADS>(A, B, M, K, N, bm, bn, tid, tx, ty,
                                          As, Bs, acc, preluA != nullptr, aA);
    if (A2)
        gemm_seg<BM, BN, BK, TM, TN, THREADS>(A2, B2, M, K2, N, bm, bn, tid, tx, ty,
                                              As, Bs, acc, false, 0.f);

    const float al = alphaOut ? alphaOut[0] : 0.f;
    #pragma unroll
    for (int i = 0; i < TM; i++) {
        int r = bm + ty * TM + i;
        if (r >= M) return;
        #pragma unroll
        for (int j = 0; j < TN; j += 4) {
            int c = bn + tx * TN + j;
            float4 v = make_float4(acc[i][j], acc[i][j + 1], acc[i][j + 2], acc[i][j + 3]);
            if (alphaOut) {
                v.x = (v.x >= 0.f) ? v.x : al * v.x;
                v.y = (v.y >= 0.f) ? v.y : al * v.y;
                v.z = (v.z >= 0.f) ? v.z : al * v.z;
                v.w = (v.w >= 0.f) ? v.w : al * v.w;
            }
            *reinterpret_cast<float4*>(&D[(size_t)r * N + c]) = v;
        }
    }
}

// ---------------- edge scatter: agg[dst] += ew * h[src] ----------------
__device__ __forceinline__ void red_add_v4(float* p, float4 v) {
    asm volatile("red.global.add.v4.f32 [%0], {%1, %2, %3, %4};"
                 :: "l"(p), "f"(v.x), "f"(v.y), "f"(v.z), "f"(v.w) : "memory");
}

template<int C>
__global__ void scatter_k(const float* __restrict__ h, const int* __restrict__ src,
                          const int* __restrict__ dst, const float* __restrict__ ew,
                          float* __restrict__ agg, int E)
{
    int gw = blockIdx.x * (blockDim.x >> 5) + (threadIdx.x >> 5);
    int lane = threadIdx.x & 31;
    if (gw >= E) return;
    int s = __ldg(src + gw);
    int d = __ldg(dst + gw);
    float w = __ldg(ew + gw);
    const float4* hr = reinterpret_cast<const float4*>(h + (size_t)s * C);
    float* ar = agg + (size_t)d * C;
    #pragma unroll
    for (int i = 0; i < C / 128; i++) {
        int idx = lane + i * 32;
        float4 v = __ldg(hr + idx);
        v.x *= w; v.y *= w; v.z *= w; v.w *= w;
        red_add_v4(ar + idx * 4, v);
    }
}

// ---------------- elementwise helpers ----------------
__global__ void binit4_k(float4* __restrict__ agg, const float4* __restrict__ b,
                         int total4, int c4mask)
{
    int i = blockIdx.x * blockDim.x + threadIdx.x;
    if (i < total4) agg[i] = b[i & c4mask];
}

__global__ void prelu4_k(const float4* __restrict__ in, float4* __restrict__ out,
                         int n4, const float* __restrict__ a)
{
    int i = blockIdx.x * blockDim.x + threadIdx.x;
    if (i < n4) {
        float al = a[0];
        float4 v = in[i];
        v.x = (v.x >= 0.f) ? v.x : al * v.x;
        v.y = (v.y >= 0.f) ? v.y : al * v.y;
        v.z = (v.z >= 0.f) ? v.z : al * v.z;
        v.w = (v.w >= 0.f) ? v.w : al * v.w;
        out[i] = v;
    }
}

// ---------------- launch ----------------
extern "C" void kernel_launch(void* const* d_in, const int* in_sizes, int n_in,
                              void* d_out, int out_size)
{
    const float* seq  = (const float*)d_in[0];
    const int*   ei   = (const int*)  d_in[1];
    const float* ew   = (const float*)d_in[2];
    const float* W1   = (const float*)d_in[3];
    const float* b1   = (const float*)d_in[4];
    const float* W2   = (const float*)d_in[5];
    const float* b2   = (const float*)d_in[6];
    const float* a1   = (const float*)d_in[7];
    const float* a2   = (const float*)d_in[8];
    const float* a3   = (const float*)d_in[9];
    const float* Wfc1 = (const float*)d_in[10];
    const float* Wfc2 = (const float*)d_in[11];
    const float* Wfc3 = (const float*)d_in[12];
    const float* Wfc4 = (const float*)d_in[13];

    const int N = in_sizes[0] / INC;     // 50000
    const int E = in_sizes[2];           // 800000
    const int* src = ei;
    const int* dst = ei + E;

    float *H1, *A1, *H2, *A2, *U, *PA, *PB;
    cudaGetSymbolAddress((void**)&H1, g_H1);
    cudaGetSymbolAddress((void**)&A1, g_A1);
    cudaGetSymbolAddress((void**)&H2, g_H2);
    cudaGetSymbolAddress((void**)&A2, g_A2);
    cudaGetSymbolAddress((void**)&U,  g_U);
    cudaGetSymbolAddress((void**)&PA, g_PA);
    cudaGetSymbolAddress((void**)&PB, g_PB);

    float* outx = (float*)d_out;                      // x:     [N,128]
    float* outf = (float*)d_out + (size_t)N * HC;     // feat1: [N,64]

    const dim3 blk(256);
    const int gy = (N + 127) / 128;                   // 391

    // ---- fold the FC head (re-associated): U = Wfc3@Wfc4; PA = Wfc2@U_top; PB = Wfc1@U_bot ----
    sgemm_k<128,64,16,8,4><<<dim3(1, 4), blk>>>(Wfc3, Wfc4, HC,   nullptr, nullptr, 0, U,  4*HC, OUTC, nullptr, nullptr);
    sgemm_k<128,64,16,8,4><<<dim3(1, 2), blk>>>(Wfc2, U,    2*HC, nullptr, nullptr, 0, PA, 2*HC, OUTC, nullptr, nullptr);
    sgemm_k<128,64,16,8,4><<<dim3(1, 1), blk>>>(Wfc1, U + 2*HC*OUTC, 2*HC, nullptr, nullptr, 0, PB, HC, OUTC, nullptr, nullptr);

    // ---- GCN layer 1: A1 = scatter(ew * (seq@W1)[src] -> dst) + b1  (prelu deferred) ----
    sgemm_k<128,128,16,8,8><<<dim3(2, gy), blk>>>(seq, W1, INC, nullptr, nullptr, 0, H1, N, 2*HC, nullptr, nullptr);
    {
        int total4 = N * 2 * HC / 4;
        binit4_k<<<(total4 + 255) / 256, blk>>>((float4*)A1, (const float4*)b1, total4, (2*HC/4) - 1);
    }
    scatter_k<2*HC><<<(E + 7) / 8, blk>>>(H1, src, dst, ew, A1, E);

    // ---- GCN layer 2: H2 = prelu(A1, a1) @ W2  (PReLU fused into A-load) ----
    sgemm_k<128,128,16,8,8><<<dim3(1, gy), blk>>>(A1, W2, 2*HC, nullptr, nullptr, 0, H2, N, HC, a1, nullptr);
    {
        int total4 = N * HC / 4;
        binit4_k<<<(total4 + 255) / 256, blk>>>((float4*)A2, (const float4*)b2, total4, (HC/4) - 1);
    }
    scatter_k<HC><<<(E + 7) / 8, blk>>>(H2, src, dst, ew, A2, E);
    {
        int n4 = N * HC / 4;
        prelu4_k<<<(n4 + 255) / 256, blk>>>((const float4*)A2, (float4*)outx, n4, a2);
    }

    // ---- fused head: feat1 = prelu(seq@PA + x@PB, a3), single kernel ----
    sgemm_k<128,64,16,8,4><<<dim3(1, gy), blk>>>(seq, PA, INC, outx, PB, HC, outf, N, OUTC, nullptr, a3);
}

// round 6
// speedup vs baseline: 2.1174x; 1.1704x over previous
#include <cuda_runtime.h>
#include <cstdint>

#define NNODES 50000
#define INC    256
#define HC     128
#define OUTC   64

// ---------------- scratch (static __device__ — no allocations) ----------------
__device__ float g_H1[NNODES * 2 * HC];   // seq@W1          [N,256]
__device__ float g_A1[NNODES * 2 * HC];   // agg1 (pre-act)  [N,256]
__device__ float g_H2[NNODES * HC];       // prelu(A1)@W2    [N,128]
__device__ float g_A2[NNODES * HC];       // agg2            [N,128]
__device__ float g_U [4 * HC * OUTC];     // Wfc3@Wfc4       [512,64]
__device__ float g_PA[2 * HC * OUTC];     // Wfc2@U_top      [256,64]
__device__ float g_PB[HC * OUTC];         // Wfc1@U_bot      [128,64]

// ---------------- cp.async helpers ----------------
__device__ __forceinline__ void cp_async16(void* smem_dst, const void* gmem_src) {
    uint32_t s = (uint32_t)__cvta_generic_to_shared(smem_dst);
    asm volatile("cp.async.cg.shared.global [%0], [%1], 16;\n" :: "r"(s), "l"(gmem_src));
}
__device__ __forceinline__ void cp_async_commit() {
    asm volatile("cp.async.commit_group;\n" ::: "memory");
}
__device__ __forceinline__ void cp_async_wait0() {
    asm volatile("cp.async.wait_group 0;\n" ::: "memory");
}

// ---------------- pipelined fp32 GEMM segment ----------------
// acc += op(A)[M,K] @ B[K,N] for this block tile.
// A: LDG->reg->STS (transposed into As[k][m], optional PReLU).
// B: cp.async direct gmem->smem (row layout matches).
// Requires K % BK == 0, N % BN == 0 (B rows never OOB). M arbitrary (A guarded).
template<int BM, int BN, int BK, int TM, int TN, int THREADS>
__device__ __forceinline__ void gemm_seg(
    const float* __restrict__ A, const float* __restrict__ B,
    int M, int K, int N, int bm, int bn, int tid, int tx, int ty,
    float (&As)[2][BK][BM], float (&Bs)[2][BK][BN],
    float (&acc)[TM][TN], bool doPrelu, float aA)
{
    constexpr int A4 = BM * BK / 4;
    constexpr int B4 = BK * BN / 4;
    constexpr int AL = A4 / THREADS;
    constexpr int BL = B4 / THREADS;
    static_assert(A4 % THREADS == 0 && B4 % THREADS == 0, "tile/thread mismatch");

    float4 aReg[AL];
    const int nt = K / BK;

    auto loadA = [&](int t) {
        #pragma unroll
        for (int l = 0; l < AL; l++) {
            int idx = tid + l * THREADS;
            int r   = idx / (BK / 4);
            int kc  = (idx % (BK / 4)) * 4;
            int row = bm + r;
            float4 v = make_float4(0.f, 0.f, 0.f, 0.f);
            if (row < M)
                v = *reinterpret_cast<const float4*>(&A[(size_t)row * K + t * BK + kc]);
            aReg[l] = v;
        }
    };
    auto storeA = [&](int buf) {
        #pragma unroll
        for (int l = 0; l < AL; l++) {
            int idx = tid + l * THREADS;
            int r   = idx / (BK / 4);
            int kc  = (idx % (BK / 4)) * 4;
            float4 v = aReg[l];
            if (doPrelu) {
                v.x = (v.x >= 0.f) ? v.x : aA * v.x;
                v.y = (v.y >= 0.f) ? v.y : aA * v.y;
                v.z = (v.z >= 0.f) ? v.z : aA * v.z;
                v.w = (v.w >= 0.f) ? v.w : aA * v.w;
            }
            As[buf][kc + 0][r] = v.x;
            As[buf][kc + 1][r] = v.y;
            As[buf][kc + 2][r] = v.z;
            As[buf][kc + 3][r] = v.w;
        }
    };
    auto loadBasync = [&](int t, int buf) {
        #pragma unroll
        for (int l = 0; l < BL; l++) {
            int idx = tid + l * THREADS;
            int kk  = idx / (BN / 4);
            int c   = (idx % (BN / 4)) * 4;
            cp_async16(&Bs[buf][kk][c], &B[(size_t)(t * BK + kk) * N + bn + c]);
        }
        cp_async_commit();
    };

    // prologue: tile 0
    loadA(0);
    loadBasync(0, 0);
    storeA(0);
    cp_async_wait0();
    __syncthreads();

    int buf = 0;
    for (int t = 0; t < nt; t++) {
        if (t + 1 < nt) {
            loadA(t + 1);                 // LDG in flight over compute
            loadBasync(t + 1, buf ^ 1);   // cp.async in flight over compute
        }
        #pragma unroll
        for (int kk = 0; kk < BK; kk++) {
            float a[TM], b[TN];
            #pragma unroll
            for (int i = 0; i < TM / 4; i++)
                *reinterpret_cast<float4*>(&a[i * 4]) =
                    *reinterpret_cast<const float4*>(&As[buf][kk][ty * TM + i * 4]);
            #pragma unroll
            for (int j = 0; j < TN / 4; j++)
                *reinterpret_cast<float4*>(&b[j * 4]) =
                    *reinterpret_cast<const float4*>(&Bs[buf][kk][tx * TN + j * 4]);
            #pragma unroll
            for (int i = 0; i < TM; i++)
                #pragma unroll
                for (int j = 0; j < TN; j++)
                    acc[i][j] += a[i] * b[j];
        }
        if (t + 1 < nt) storeA(buf ^ 1);
        cp_async_wait0();
        __syncthreads();
        buf ^= 1;
    }
}

// ---------------- GEMM kernel: D = op(A)@B [+ A2@B2] (then PReLU) ----------------
template<int BM, int BN, int BK, int TM, int TN>
__global__ void __launch_bounds__(256, 2)
sgemm_k(const float* __restrict__ A, const float* __restrict__ B, int K,
        const float* __restrict__ A2, const float* __restrict__ B2, int K2,
        float* __restrict__ D, int M, int N,
        const float* __restrict__ preluA, const float* __restrict__ alphaOut)
{
    constexpr int THREADS = (BM / TM) * (BN / TN);
    static_assert(THREADS == 256, "block must be 256 threads");
    __shared__ float As[2][BK][BM];
    __shared__ float Bs[2][BK][BN];

    const int bm = blockIdx.y * BM, bn = blockIdx.x * BN;
    const int tid = threadIdx.x;
    const int tx = tid % (BN / TN);
    const int ty = tid / (BN / TN);

    float acc[TM][TN] = {};
    const float aA = preluA ? preluA[0] : 0.f;

    gemm_seg<BM, BN, BK, TM, TN, THREADS>(A, B, M, K, N, bm, bn, tid, tx, ty,
                                          As, Bs, acc, preluA != nullptr, aA);
    if (A2)
        gemm_seg<BM, BN, BK, TM, TN, THREADS>(A2, B2, M, K2, N, bm, bn, tid, tx, ty,
                                              As, Bs, acc, false, 0.f);

    const float al = alphaOut ? alphaOut[0] : 0.f;
    #pragma unroll
    for (int i = 0; i < TM; i++) {
        int r = bm + ty * TM + i;
        if (r >= M) return;
        #pragma unroll
        for (int j = 0; j < TN; j += 4) {
            int c = bn + tx * TN + j;
            float4 v = make_float4(acc[i][j], acc[i][j + 1], acc[i][j + 2], acc[i][j + 3]);
            if (alphaOut) {
                v.x = (v.x >= 0.f) ? v.x : al * v.x;
                v.y = (v.y >= 0.f) ? v.y : al * v.y;
                v.z = (v.z >= 0.f) ? v.z : al * v.z;
                v.w = (v.w >= 0.f) ? v.w : al * v.w;
            }
            *reinterpret_cast<float4*>(&D[(size_t)r * N + c]) = v;
        }
    }
}

// ---------------- edge scatter: agg[dst] += ew * h[src] ----------------
__device__ __forceinline__ void red_add_v4(float* p, float4 v) {
    asm volatile("red.global.add.v4.f32 [%0], {%1, %2, %3, %4};"
                 :: "l"(p), "f"(v.x), "f"(v.y), "f"(v.z), "f"(v.w) : "memory");
}

template<int C>
__global__ void scatter_k(const float* __restrict__ h, const int* __restrict__ src,
                          const int* __restrict__ dst, const float* __restrict__ ew,
                          float* __restrict__ agg, int E)
{
    int gw = blockIdx.x * (blockDim.x >> 5) + (threadIdx.x >> 5);
    int lane = threadIdx.x & 31;
    if (gw >= E) return;
    int s = __ldg(src + gw);
    int d = __ldg(dst + gw);
    float w = __ldg(ew + gw);
    const float4* hr = reinterpret_cast<const float4*>(h + (size_t)s * C);
    float* ar = agg + (size_t)d * C;
    #pragma unroll
    for (int i = 0; i < C / 128; i++) {
        int idx = lane + i * 32;
        float4 v = __ldg(hr + idx);
        v.x *= w; v.y *= w; v.z *= w; v.w *= w;
        red_add_v4(ar + idx * 4, v);
    }
}

// ---------------- elementwise helpers ----------------
__global__ void binit4_k(float4* __restrict__ agg, const float4* __restrict__ b,
                         int total4, int c4mask)
{
    int i = blockIdx.x * blockDim.x + threadIdx.x;
    if (i < total4) agg[i] = b[i & c4mask];
}

__global__ void prelu4_k(const float4* __restrict__ in, float4* __restrict__ out,
                         int n4, const float* __restrict__ a)
{
    int i = blockIdx.x * blockDim.x + threadIdx.x;
    if (i < n4) {
        float al = a[0];
        float4 v = in[i];
        v.x = (v.x >= 0.f) ? v.x : al * v.x;
        v.y = (v.y >= 0.f) ? v.y : al * v.y;
        v.z = (v.z >= 0.f) ? v.z : al * v.z;
        v.w = (v.w >= 0.f) ? v.w : al * v.w;
        out[i] = v;
    }
}

// ---------------- launch ----------------
extern "C" void kernel_launch(void* const* d_in, const int* in_sizes, int n_in,
                              void* d_out, int out_size)
{
    const float* seq  = (const float*)d_in[0];
    const int*   ei   = (const int*)  d_in[1];
    const float* ew   = (const float*)d_in[2];
    const float* W1   = (const float*)d_in[3];
    const float* b1   = (const float*)d_in[4];
    const float* W2   = (const float*)d_in[5];
    const float* b2   = (const float*)d_in[6];
    const float* a1   = (const float*)d_in[7];
    const float* a2   = (const float*)d_in[8];
    const float* a3   = (const float*)d_in[9];
    const float* Wfc1 = (const float*)d_in[10];
    const float* Wfc2 = (const float*)d_in[11];
    const float* Wfc3 = (const float*)d_in[12];
    const float* Wfc4 = (const float*)d_in[13];

    const int N = in_sizes[0] / INC;     // 50000
    const int E = in_sizes[2];           // 800000
    const int* src = ei;
    const int* dst = ei + E;

    float *H1, *A1, *H2, *A2, *U, *PA, *PB;
    cudaGetSymbolAddress((void**)&H1, g_H1);
    cudaGetSymbolAddress((void**)&A1, g_A1);
    cudaGetSymbolAddress((void**)&H2, g_H2);
    cudaGetSymbolAddress((void**)&A2, g_A2);
    cudaGetSymbolAddress((void**)&U,  g_U);
    cudaGetSymbolAddress((void**)&PA, g_PA);
    cudaGetSymbolAddress((void**)&PB, g_PB);

    float* outx = (float*)d_out;                      // x:     [N,128]
    float* outf = (float*)d_out + (size_t)N * HC;     // feat1: [N,64]

    const dim3 blk(256);
    const int gy = (N + 127) / 128;                   // 391

    // ---- fold the FC head: U = Wfc3@Wfc4; PA = Wfc2@U_top; PB = Wfc1@U_bot ----
    sgemm_k<128,64,16,8,4><<<dim3(1, 4), blk>>>(Wfc3, Wfc4, HC,   nullptr, nullptr, 0, U,  4*HC, OUTC, nullptr, nullptr);
    sgemm_k<128,64,16,8,4><<<dim3(1, 2), blk>>>(Wfc2, U,    2*HC, nullptr, nullptr, 0, PA, 2*HC, OUTC, nullptr, nullptr);
    sgemm_k<128,64,16,8,4><<<dim3(1, 1), blk>>>(Wfc1, U + 2*HC*OUTC, 2*HC, nullptr, nullptr, 0, PB, HC, OUTC, nullptr, nullptr);

    // ---- GCN layer 1: A1 = scatter(ew * (seq@W1)[src] -> dst) + b1  (prelu deferred) ----
    sgemm_k<128,128,16,8,8><<<dim3(2, gy), blk>>>(seq, W1, INC, nullptr, nullptr, 0, H1, N, 2*HC, nullptr, nullptr);
    {
        int total4 = N * 2 * HC / 4;
        binit4_k<<<(total4 + 255) / 256, blk>>>((float4*)A1, (const float4*)b1, total4, (2*HC/4) - 1);
    }
    scatter_k<2*HC><<<(E + 7) / 8, blk>>>(H1, src, dst, ew, A1, E);

    // ---- GCN layer 2: H2 = prelu(A1, a1) @ W2  (PReLU fused into A-load) ----
    sgemm_k<128,128,16,8,8><<<dim3(1, gy), blk>>>(A1, W2, 2*HC, nullptr, nullptr, 0, H2, N, HC, a1, nullptr);
    {
        int total4 = N * HC / 4;
        binit4_k<<<(total4 + 255) / 256, blk>>>((float4*)A2, (const float4*)b2, total4, (HC/4) - 1);
    }
    scatter_k<HC><<<(E + 7) / 8, blk>>>(H2, src, dst, ew, A2, E);
    {
        int n4 = N * HC / 4;
        prelu4_k<<<(n4 + 255) / 256, blk>>>((const float4*)A2, (float4*)outx, n4, a2);
    }

    // ---- fused head: feat1 = prelu(seq@PA + x@PB, a3), single kernel ----
    sgemm_k<128,64,16,8,4><<<dim3(1, gy), blk>>>(seq, PA, INC, outx, PB, HC, outf, N, OUTC, nullptr, a3);
}

// round 8
// speedup vs baseline: 2.6661x; 1.2591x over previous
#include <cuda_runtime.h>
#include <cuda_bf16.h>
#include <cstdint>

#define NNODES 50000
#define INC    256
#define HC     128
#define OUTC   64

// ---------------- scratch (static __device__ — no allocations) ----------------
__device__ float g_H1[NNODES * 2 * HC];   // seq@W1          [N,256]
__device__ float g_A1[NNODES * 2 * HC];   // agg1 (pre-act)  [N,256]
__device__ float g_H2[NNODES * HC];       // prelu(A1)@W2    [N,128]
__device__ float g_A2[NNODES * HC];       // agg2            [N,128]
__device__ float g_U [4 * HC * OUTC];     // Wfc3@Wfc4       [512,64]
__device__ float g_PA[2 * HC * OUTC];     // Wfc2@U_top      [256,64]
__device__ float g_PB[HC * OUTC];         // Wfc1@U_bot      [128,64]

// packed bf16x2 weight splits: layout [n][K/2] (k-pairs contiguous per output col)
__device__ uint32_t g_W1h[2*HC * INC/2], g_W1l[2*HC * INC/2];   // N=256, Kp=128
__device__ uint32_t g_W2h[HC * 2*HC/2],  g_W2l[HC * 2*HC/2];    // N=128, Kp=128
__device__ uint32_t g_PAh[OUTC * INC/2], g_PAl[OUTC * INC/2];   // N=64,  Kp=128
__device__ uint32_t g_PBh[OUTC * HC/2],  g_PBl[OUTC * HC/2];    // N=64,  Kp=64

// ---------------- small helpers ----------------
__device__ __forceinline__ void cp_async16(void* smem_dst, const void* gmem_src) {
    uint32_t s = (uint32_t)__cvta_generic_to_shared(smem_dst);
    asm volatile("cp.async.cg.shared.global [%0], [%1], 16;\n" :: "r"(s), "l"(gmem_src));
}
__device__ __forceinline__ void cp_async_commit() {
    asm volatile("cp.async.commit_group;\n" ::: "memory");
}
__device__ __forceinline__ void cp_async_wait0() {
    asm volatile("cp.async.wait_group 0;\n" ::: "memory");
}

__device__ __forceinline__ uint32_t pk2(float e, float o) {   // e -> low 16, o -> high 16
    __nv_bfloat162 p = __floats2bfloat162_rn(e, o);
    return *reinterpret_cast<uint32_t*>(&p);
}

__device__ __forceinline__ void mma_bf16(float d[4],
    uint32_t a0, uint32_t a1, uint32_t a2, uint32_t a3, uint32_t b0, uint32_t b1)
{
    asm volatile(
        "mma.sync.aligned.m16n8k16.row.col.f32.bf16.bf16.f32 "
        "{%0,%1,%2,%3}, {%4,%5,%6,%7}, {%8,%9}, {%0,%1,%2,%3};\n"
        : "+f"(d[0]), "+f"(d[1]), "+f"(d[2]), "+f"(d[3])
        : "r"(a0), "r"(a1), "r"(a2), "r"(a3), "r"(b0), "r"(b1));
}

// ---------------- weight split prep: W[K][N] f32 -> hi/lo packed [N][K/2] ----------------
__global__ void split_w_k(const float* __restrict__ W, uint32_t* __restrict__ hi,
                          uint32_t* __restrict__ lo, int Kp, int N)
{
    int idx = blockIdx.x * blockDim.x + threadIdx.x;
    if (idx >= N * Kp) return;
    int n = idx / Kp, kp = idx % Kp;
    float v0 = W[(size_t)(2 * kp) * N + n];
    float v1 = W[(size_t)(2 * kp + 1) * N + n];
    float h0 = __bfloat162float(__float2bfloat16(v0));
    float h1 = __bfloat162float(__float2bfloat16(v1));
    hi[idx] = pk2(h0, h1);
    lo[idx] = pk2(v0 - h0, v1 - h1);
}

// ---------------- bf16-split tensor-core GEMM ----------------
// Tile 128x64x32, 256 threads = 8 warps (4 m-warps x 2 n-warps), warp tile m32n32.
// D = op(A)@B [+ A2@B2] (then PReLU). B given as pre-split packed bf16x2 [n][K/2].
#define ASTR 20   // k-pairs per A smem row (16 used + 4 pad)
#define BSTR 20   // k-pairs per B smem row (16 used + 4 pad)

struct SmemTC {
    __align__(16) uint32_t Ah[128 * ASTR];
    __align__(16) uint32_t Al[128 * ASTR];
    __align__(16) uint32_t B[2][2][64 * BSTR];   // [buf][hi/lo][n*BSTR + kp]
};

__device__ __forceinline__ void gemm_bf_seg(
    const float* __restrict__ A, const uint32_t* __restrict__ Bh,
    const uint32_t* __restrict__ Bl, int M, int K,
    int bm, int bn, int tid, SmemTC* sm, float acc[2][4][4],
    bool doPrelu, float aA)
{
    const int lane = tid & 31, warp = tid >> 5;
    const int wm = warp & 3, wn = warp >> 2;
    const int g = lane >> 2, tq = lane & 3;
    const int Kp = K >> 1;
    const int nt = K / 32;

    float4 aS[4];

    auto stageA = [&](int t) {
        #pragma unroll
        for (int l = 0; l < 4; l++) {
            int idx = tid + l * 256;          // 0..1023 over 128 rows x 8 quads
            int r = idx >> 3, q = idx & 7;
            int row = bm + r;
            float4 v = make_float4(0.f, 0.f, 0.f, 0.f);
            if (row < M)
                v = *reinterpret_cast<const float4*>(&A[(size_t)row * K + t * 32 + q * 4]);
            aS[l] = v;
        }
    };
    auto storeA = [&]() {
        #pragma unroll
        for (int l = 0; l < 4; l++) {
            int idx = tid + l * 256;
            int r = idx >> 3, q = idx & 7;
            float4 v = aS[l];
            if (doPrelu) {
                v.x = (v.x >= 0.f) ? v.x : aA * v.x;
                v.y = (v.y >= 0.f) ? v.y : aA * v.y;
                v.z = (v.z >= 0.f) ? v.z : aA * v.z;
                v.w = (v.w >= 0.f) ? v.w : aA * v.w;
            }
            float hx = __bfloat162float(__float2bfloat16(v.x));
            float hy = __bfloat162float(__float2bfloat16(v.y));
            float hz = __bfloat162float(__float2bfloat16(v.z));
            float hw = __bfloat162float(__float2bfloat16(v.w));
            uint2 hp = make_uint2(pk2(hx, hy), pk2(hz, hw));
            uint2 lp = make_uint2(pk2(v.x - hx, v.y - hy), pk2(v.z - hz, v.w - hw));
            *reinterpret_cast<uint2*>(&sm->Ah[r * ASTR + q * 2]) = hp;
            *reinterpret_cast<uint2*>(&sm->Al[r * ASTR + q * 2]) = lp;
        }
    };
    auto cpB = [&](int t, int buf) {
        int n = tid >> 2;                     // 0..63
        int c = (tid & 3) * 4;                // 0,4,8,12 (k-pairs)
        const uint32_t* sh = Bh + (size_t)(bn + n) * Kp + t * 16 + c;
        const uint32_t* sl = Bl + (size_t)(bn + n) * Kp + t * 16 + c;
        cp_async16(&sm->B[buf][0][n * BSTR + c], sh);
        cp_async16(&sm->B[buf][1][n * BSTR + c], sl);
        cp_async_commit();
    };

    // prologue
    stageA(0);
    cpB(0, 0);
    storeA();
    cp_async_wait0();
    __syncthreads();

    int buf = 0;
    for (int t = 0; t < nt; t++) {
        bool more = (t + 1 < nt);
        if (more) { stageA(t + 1); cpB(t + 1, buf ^ 1); }

        const uint32_t* aH = sm->Ah + (wm * 32 + g) * ASTR;
        const uint32_t* aL = sm->Al + (wm * 32 + g) * ASTR;
        const uint32_t* bH = sm->B[buf][0] + (wn * 32 + g) * BSTR;
        const uint32_t* bL = sm->B[buf][1] + (wn * 32 + g) * BSTR;

        #pragma unroll
        for (int kk = 0; kk < 2; kk++) {
            int kb = kk * 8;
            uint32_t ah[2][4], alr[2][4];
            #pragma unroll
            for (int im = 0; im < 2; im++) {
                const uint32_t* pH = aH + im * 16 * ASTR;
                const uint32_t* pL = aL + im * 16 * ASTR;
                ah[im][0] = pH[kb + tq];
                ah[im][1] = pH[8 * ASTR + kb + tq];
                ah[im][2] = pH[kb + tq + 4];
                ah[im][3] = pH[8 * ASTR + kb + tq + 4];
                alr[im][0] = pL[kb + tq];
                alr[im][1] = pL[8 * ASTR + kb + tq];
                alr[im][2] = pL[kb + tq + 4];
                alr[im][3] = pL[8 * ASTR + kb + tq + 4];
            }
            uint32_t bh[4][2], blr[4][2];
            #pragma unroll
            for (int jn = 0; jn < 4; jn++) {
                const uint32_t* qH = bH + jn * 8 * BSTR;
                const uint32_t* qL = bL + jn * 8 * BSTR;
                bh[jn][0] = qH[kb + tq];
                bh[jn][1] = qH[kb + tq + 4];
                blr[jn][0] = qL[kb + tq];
                blr[jn][1] = qL[kb + tq + 4];
            }
            #pragma unroll
            for (int im = 0; im < 2; im++)
                #pragma unroll
                for (int jn = 0; jn < 4; jn++) {
                    mma_bf16(acc[im][jn], alr[im][0], alr[im][1], alr[im][2], alr[im][3],
                             bh[jn][0], bh[jn][1]);
                    mma_bf16(acc[im][jn], ah[im][0], ah[im][1], ah[im][2], ah[im][3],
                             blr[jn][0], blr[jn][1]);
                    mma_bf16(acc[im][jn], ah[im][0], ah[im][1], ah[im][2], ah[im][3],
                             bh[jn][0], bh[jn][1]);
                }
        }
        __syncthreads();
        if (more) storeA();
        cp_async_wait0();
        __syncthreads();
        buf ^= 1;
    }
}

__global__ void __launch_bounds__(256, 2)
gemm_bf_k(const float* __restrict__ A, const uint32_t* __restrict__ Bh,
          const uint32_t* __restrict__ Bl, int K,
          const float* __restrict__ A2, const uint32_t* __restrict__ B2h,
          const uint32_t* __restrict__ B2l, int K2,
          float* __restrict__ D, int M, int ldD,
          const float* __restrict__ preluA, const float* __restrict__ alphaOut)
{
    __shared__ SmemTC sm;
    const int tid = threadIdx.x;
    const int bm = blockIdx.y * 128, bn = blockIdx.x * 64;

    float acc[2][4][4] = {};
    const float aA = preluA ? preluA[0] : 0.f;

    gemm_bf_seg(A, Bh, Bl, M, K, bm, bn, tid, &sm, acc, preluA != nullptr, aA);
    if (A2)
        gemm_bf_seg(A2, B2h, B2l, M, K2, bm, bn, tid, &sm, acc, false, 0.f);

    const int lane = tid & 31, warp = tid >> 5;
    const int wm = warp & 3, wn = warp >> 2;
    const int g = lane >> 2, tq = lane & 3;
    const float al = alphaOut ? alphaOut[0] : 0.f;

    #pragma unroll
    for (int im = 0; im < 2; im++)
        #pragma unroll
        for (int jn = 0; jn < 4; jn++) {
            int r0 = bm + wm * 32 + im * 16 + g;
            int c0 = bn + wn * 32 + jn * 8 + 2 * tq;
            float2 v0 = make_float2(acc[im][jn][0], acc[im][jn][1]);
            float2 v1 = make_float2(acc[im][jn][2], acc[im][jn][3]);
            if (alphaOut) {
                v0.x = (v0.x >= 0.f) ? v0.x : al * v0.x;
                v0.y = (v0.y >= 0.f) ? v0.y : al * v0.y;
                v1.x = (v1.x >= 0.f) ? v1.x : al * v1.x;
                v1.y = (v1.y >= 0.f) ? v1.y : al * v1.y;
            }
            if (r0 < M)     *reinterpret_cast<float2*>(&D[(size_t)r0 * ldD + c0]) = v0;
            if (r0 + 8 < M) *reinterpret_cast<float2*>(&D[(size_t)(r0 + 8) * ldD + c0]) = v1;
        }
}

// ---------------- SIMT fp32 GEMM for tiny fold matrices ----------------
template<int BM, int BN, int BK, int TM, int TN>
__global__ void __launch_bounds__(256, 2)
sgemm_k(const float* __restrict__ A, const float* __restrict__ B, int K,
        float* __restrict__ D, int M, int N)
{
    constexpr int THREADS = (BM / TM) * (BN / TN);
    static_assert(THREADS == 256, "block must be 256 threads");
    __shared__ float As[2][BK][BM];
    __shared__ float Bs[2][BK][BN];
    constexpr int A4 = BM * BK / 4, B4 = BK * BN / 4;
    constexpr int AL = A4 / THREADS, BL = B4 / THREADS;

    const int bm = blockIdx.y * BM, bn = blockIdx.x * BN;
    const int tid = threadIdx.x;
    const int tx = tid % (BN / TN), ty = tid / (BN / TN);
    float acc[TM][TN] = {};
    float4 aReg[AL], bReg[BL];
    const int nt = K / BK;

    auto loadT = [&](int t) {
        #pragma unroll
        for (int l = 0; l < AL; l++) {
            int idx = tid + l * THREADS;
            int r = idx / (BK / 4), kc = (idx % (BK / 4)) * 4;
            int row = bm + r;
            aReg[l] = (row < M) ? *reinterpret_cast<const float4*>(&A[(size_t)row * K + 0 + kc + t * BK])
                                : make_float4(0.f, 0.f, 0.f, 0.f);
        }
        #pragma unroll
        for (int l = 0; l < BL; l++) {
            int idx = tid + l * THREADS;
            int kk = idx / (BN / 4), c = (idx % (BN / 4)) * 4;
            bReg[l] = *reinterpret_cast<const float4*>(&B[(size_t)(t * BK + kk) * N + bn + c]);
        }
    };
    auto storeT = [&](int buf) {
        #pragma unroll
        for (int l = 0; l < AL; l++) {
            int idx = tid + l * THREADS;
            int r = idx / (BK / 4), kc = (idx % (BK / 4)) * 4;
            As[buf][kc + 0][r] = aReg[l].x; As[buf][kc + 1][r] = aReg[l].y;
            As[buf][kc + 2][r] = aReg[l].z; As[buf][kc + 3][r] = aReg[l].w;
        }
        #pragma unroll
        for (int l = 0; l < BL; l++) {
            int idx = tid + l * THREADS;
            int kk = idx / (BN / 4), c = (idx % (BN / 4)) * 4;
            *reinterpret_cast<float4*>(&Bs[buf][kk][c]) = bReg[l];
        }
    };

    loadT(0); storeT(0); __syncthreads();
    int buf = 0;
    for (int t = 0; t < nt; t++) {
        if (t + 1 < nt) loadT(t + 1);
        #pragma unroll
        for (int kk = 0; kk < BK; kk++) {
            float a[TM], b[TN];
            #pragma unroll
            for (int i = 0; i < TM / 4; i++)
                *reinterpret_cast<float4*>(&a[i * 4]) =
                    *reinterpret_cast<const float4*>(&As[buf][kk][ty * TM + i * 4]);
            #pragma unroll
            for (int j = 0; j < TN / 4; j++)
                *reinterpret_cast<float4*>(&b[j * 4]) =
                    *reinterpret_cast<const float4*>(&Bs[buf][kk][tx * TN + j * 4]);
            #pragma unroll
            for (int i = 0; i < TM; i++)
                #pragma unroll
                for (int j = 0; j < TN; j++)
                    acc[i][j] += a[i] * b[j];
        }
        if (t + 1 < nt) { __syncthreads(); storeT(buf ^ 1); }
        __syncthreads();
        buf ^= 1;
    }
    #pragma unroll
    for (int i = 0; i < TM; i++) {
        int r = bm + ty * TM + i;
        if (r >= M) return;
        #pragma unroll
        for (int j = 0; j < TN; j += 4) {
            int c = bn + tx * TN + j;
            *reinterpret_cast<float4*>(&D[(size_t)r * N + c]) =
                make_float4(acc[i][j], acc[i][j+1], acc[i][j+2], acc[i][j+3]);
        }
    }
}

// ---------------- edge scatter: agg[dst] += ew * h[src] ----------------
__device__ __forceinline__ void red_add_v4(float* p, float4 v) {
    asm volatile("red.global.add.v4.f32 [%0], {%1, %2, %3, %4};"
                 :: "l"(p), "f"(v.x), "f"(v.y), "f"(v.z), "f"(v.w) : "memory");
}

template<int C>
__global__ void scatter_k(const float* __restrict__ h, const int* __restrict__ src,
                          const int* __restrict__ dst, const float* __restrict__ ew,
                          float* __restrict__ agg, int E)
{
    int gw = blockIdx.x * (blockDim.x >> 5) + (threadIdx.x >> 5);
    int lane = threadIdx.x & 31;
    if (gw >= E) return;
    int s = __ldg(src + gw);
    int d = __ldg(dst + gw);
    float w = __ldg(ew + gw);
    const float4* hr = reinterpret_cast<const float4*>(h + (size_t)s * C);
    float* ar = agg + (size_t)d * C;
    #pragma unroll
    for (int i = 0; i < C / 128; i++) {
        int idx = lane + i * 32;
        float4 v = __ldg(hr + idx);
        v.x *= w; v.y *= w; v.z *= w; v.w *= w;
        red_add_v4(ar + idx * 4, v);
    }
}

// ---------------- elementwise helpers ----------------
__global__ void binit4_k(float4* __restrict__ agg, const float4* __restrict__ b,
                         int total4, int c4mask)
{
    int i = blockIdx.x * blockDim.x + threadIdx.x;
    if (i < total4) agg[i] = b[i & c4mask];
}

__global__ void prelu4_k(const float4* __restrict__ in, float4* __restrict__ out,
                         int n4, const float* __restrict__ a)
{
    int i = blockIdx.x * blockDim.x + threadIdx.x;
    if (i < n4) {
        float al = a[0];
        float4 v = in[i];
        v.x = (v.x >= 0.f) ? v.x : al * v.x;
        v.y = (v.y >= 0.f) ? v.y : al * v.y;
        v.z = (v.z >= 0.f) ? v.z : al * v.z;
        v.w = (v.w >= 0.f) ? v.w : al * v.w;
        out[i] = v;
    }
}

// ---------------- launch ----------------
extern "C" void kernel_launch(void* const* d_in, const int* in_sizes, int n_in,
                              void* d_out, int out_size)
{
    const float* seq  = (const float*)d_in[0];
    const int*   ei   = (const int*)  d_in[1];
    const float* ew   = (const float*)d_in[2];
    const float* W1   = (const float*)d_in[3];
    const float* b1   = (const float*)d_in[4];
    const float* W2   = (const float*)d_in[5];
    const float* b2   = (const float*)d_in[6];
    const float* a1   = (const float*)d_in[7];
    const float* a2   = (const float*)d_in[8];
    const float* a3   = (const float*)d_in[9];
    const float* Wfc1 = (const float*)d_in[10];
    const float* Wfc2 = (const float*)d_in[11];
    const float* Wfc3 = (const float*)d_in[12];
    const float* Wfc4 = (const float*)d_in[13];

    const int N = in_sizes[0] / INC;     // 50000
    const int E = in_sizes[2];           // 800000
    const int* src = ei;
    const int* dst = ei + E;

    float *H1, *A1, *H2, *A2, *U, *PA, *PB;
    uint32_t *W1h, *W1l, *W2h, *W2l, *PAh, *PAl, *PBh, *PBl;
    cudaGetSymbolAddress((void**)&H1, g_H1);
    cudaGetSymbolAddress((void**)&A1, g_A1);
    cudaGetSymbolAddress((void**)&H2, g_H2);
    cudaGetSymbolAddress((void**)&A2, g_A2);
    cudaGetSymbolAddress((void**)&U,  g_U);
    cudaGetSymbolAddress((void**)&PA, g_PA);
    cudaGetSymbolAddress((void**)&PB, g_PB);
    cudaGetSymbolAddress((void**)&W1h, g_W1h);
    cudaGetSymbolAddress((void**)&W1l, g_W1l);
    cudaGetSymbolAddress((void**)&W2h, g_W2h);
    cudaGetSymbolAddress((void**)&W2l, g_W2l);
    cudaGetSymbolAddress((void**)&PAh, g_PAh);
    cudaGetSymbolAddress((void**)&PAl, g_PAl);
    cudaGetSymbolAddress((void**)&PBh, g_PBh);
    cudaGetSymbolAddress((void**)&PBl, g_PBl);

    float* outx = (float*)d_out;                      // x:     [N,128]
    float* outf = (float*)d_out + (size_t)N * HC;     // feat1: [N,64]

    const dim3 blk(256);
    const int gy = (N + 127) / 128;                   // 391

    // ---- weight splits (independent of graph state) ----
    split_w_k<<<(2*HC * INC/2 + 255) / 256, blk>>>(W1, W1h, W1l, INC/2, 2*HC);
    split_w_k<<<(HC * 2*HC/2 + 255) / 256, blk>>>(W2, W2h, W2l, 2*HC/2, HC);

    // ---- fold the FC head: U = Wfc3@Wfc4; PA = Wfc2@U_top; PB = Wfc1@U_bot ----
    sgemm_k<128,64,16,8,4><<<dim3(1, 4), blk>>>(Wfc3, Wfc4, HC, U, 4*HC, OUTC);
    sgemm_k<128,64,16,8,4><<<dim3(1, 2), blk>>>(Wfc2, U, 2*HC, PA, 2*HC, OUTC);
    sgemm_k<128,64,16,8,4><<<dim3(1, 1), blk>>>(Wfc1, U + 2*HC*OUTC, 2*HC, PB, HC, OUTC);
    split_w_k<<<(OUTC * INC/2 + 255) / 256, blk>>>(PA, PAh, PAl, INC/2, OUTC);
    split_w_k<<<(OUTC * HC/2 + 255) / 256, blk>>>(PB, PBh, PBl, HC/2, OUTC);

    // ---- GCN layer 1: A1 = scatter(ew * (seq@W1)[src] -> dst) + b1 ----
    gemm_bf_k<<<dim3(4, gy), blk>>>(seq, W1h, W1l, INC,
                                    nullptr, nullptr, nullptr, 0,
                                    H1, N, 2*HC, nullptr, nullptr);
    {
        int total4 = N * 2 * HC / 4;
        binit4_k<<<(total4 + 255) / 256, blk>>>((float4*)A1, (const float4*)b1, total4, (2*HC/4) - 1);
    }
    scatter_k<2*HC><<<(E + 7) / 8, blk>>>(H1, src, dst, ew, A1, E);

    // ---- GCN layer 2: H2 = prelu(A1, a1) @ W2 ----
    gemm_bf_k<<<dim3(2, gy), blk>>>(A1, W2h, W2l, 2*HC,
                                    nullptr, nullptr, nullptr, 0,
                                    H2, N, HC, a1, nullptr);
    {
        int total4 = N * HC / 4;
        binit4_k<<<(total4 + 255) / 256, blk>>>((float4*)A2, (const float4*)b2, total4, (HC/4) - 1);
    }
    scatter_k<HC><<<(E + 7) / 8, blk>>>(H2, src, dst, ew, A2, E);
    {
        int n4 = N * HC / 4;
        prelu4_k<<<(n4 + 255) / 256, blk>>>((const float4*)A2, (float4*)outx, n4, a2);
    }

    // ---- fused head: feat1 = prelu(seq@PA + x@PB, a3), single kernel ----
    gemm_bf_k<<<dim3(1, gy), blk>>>(seq, PAh, PAl, INC,
                                    outx, PBh, PBl, HC,
                                    outf, N, OUTC, nullptr, a3);
}

// round 9
// speedup vs baseline: 3.8030x; 1.4265x over previous
#include <cuda_runtime.h>
#include <cuda_bf16.h>
#include <cstdint>

#define NNODES 50000
#define EMAX   800000
#define INC    256
#define HC     128
#define OUTC   64

// ---------------- scratch (static __device__ — no allocations) ----------------
__device__ float g_H1[NNODES * 2 * HC];   // seq@W1            [N,256]
__device__ float g_A1[NNODES * 2 * HC];   // agg1 (pre-act)    [N,256]
__device__ float g_H2[NNODES * HC];       // prelu(A1)@W2      [N,128]

// CSR build state
__device__ int g_off[NNODES + 1];
__device__ int g_cnt[NNODES];             // histogram, then fill cursor
__device__ int g_perm[EMAX];
__device__ int g_bsum[256];

// packed bf16x2 weight splits: layout [n][K/2]
__device__ uint32_t g_W1h[2*HC * INC/2], g_W1l[2*HC * INC/2];
__device__ uint32_t g_W2h[HC * 2*HC/2],  g_W2l[HC * 2*HC/2];
__device__ uint32_t g_PAh[OUTC * INC/2], g_PAl[OUTC * INC/2];
__device__ uint32_t g_PBh[OUTC * HC/2],  g_PBl[OUTC * HC/2];

// ---------------- small helpers ----------------
__device__ __forceinline__ void cp_async16(void* smem_dst, const void* gmem_src) {
    uint32_t s = (uint32_t)__cvta_generic_to_shared(smem_dst);
    asm volatile("cp.async.cg.shared.global [%0], [%1], 16;\n" :: "r"(s), "l"(gmem_src));
}
__device__ __forceinline__ void cp_async_commit() {
    asm volatile("cp.async.commit_group;\n" ::: "memory");
}
__device__ __forceinline__ void cp_async_wait0() {
    asm volatile("cp.async.wait_group 0;\n" ::: "memory");
}
__device__ __forceinline__ uint32_t pk2(float e, float o) {   // e->low16, o->high16
    __nv_bfloat162 p = __floats2bfloat162_rn(e, o);
    return *reinterpret_cast<uint32_t*>(&p);
}
__device__ __forceinline__ void mma_bf16(float d[4],
    uint32_t a0, uint32_t a1, uint32_t a2, uint32_t a3, uint32_t b0, uint32_t b1)
{
    asm volatile(
        "mma.sync.aligned.m16n8k16.row.col.f32.bf16.bf16.f32 "
        "{%0,%1,%2,%3}, {%4,%5,%6,%7}, {%8,%9}, {%0,%1,%2,%3};\n"
        : "+f"(d[0]), "+f"(d[1]), "+f"(d[2]), "+f"(d[3])
        : "r"(a0), "r"(a1), "r"(a2), "r"(a3), "r"(b0), "r"(b1));
}

// ---------------- CSR build ----------------
__global__ void zero_cnt_k(int* __restrict__ cnt, int n) {
    int i = blockIdx.x * blockDim.x + threadIdx.x;
    if (i < n) cnt[i] = 0;
}
__global__ void hist_k(const int* __restrict__ dst, int* __restrict__ cnt, int E) {
    int e = blockIdx.x * blockDim.x + threadIdx.x;
    if (e < E) atomicAdd(&cnt[dst[e]], 1);
}
__global__ void scan1_k(const int* __restrict__ cnt, int* __restrict__ off,
                        int* __restrict__ bsum, int n)
{
    __shared__ int s[256];
    int tid = threadIdx.x;
    int i = blockIdx.x * 256 + tid;
    int v = (i < n) ? cnt[i] : 0;
    s[tid] = v; __syncthreads();
    #pragma unroll
    for (int d = 1; d < 256; d <<= 1) {
        int t = (tid >= d) ? s[tid - d] : 0;
        __syncthreads();
        s[tid] += t;
        __syncthreads();
    }
    if (i < n) off[i] = s[tid] - v;        // exclusive within block
    if (tid == 255) bsum[blockIdx.x] = s[255];
}
__global__ void scan2_k(int* __restrict__ bsum, int nb)
{
    __shared__ int s[256];
    int tid = threadIdx.x;
    int v = (tid < nb) ? bsum[tid] : 0;
    s[tid] = v; __syncthreads();
    #pragma unroll
    for (int d = 1; d < 256; d <<= 1) {
        int t = (tid >= d) ? s[tid - d] : 0;
        __syncthreads();
        s[tid] += t;
        __syncthreads();
    }
    if (tid < nb) bsum[tid] = s[tid] - v;  // exclusive
}
__global__ void scan3_k(int* __restrict__ off, const int* __restrict__ bsum,
                        int* __restrict__ cnt, int n, int E)
{
    int i = blockIdx.x * blockDim.x + threadIdx.x;
    if (i < n) {
        int o = off[i] + bsum[i >> 8];
        off[i] = o;
        cnt[i] = o;                        // fill cursor
    }
    if (i == 0) off[n] = E;
}
__global__ void fill_k(const int* __restrict__ dst, int* __restrict__ cnt,
                       int* __restrict__ perm, int E)
{
    int e = blockIdx.x * blockDim.x + threadIdx.x;
    if (e < E) {
        int p = atomicAdd(&cnt[dst[e]], 1);
        perm[p] = e;
    }
}

// ---------------- CSR aggregation: out[n] = (bias + sum ew*h[src]) [prelu] ----------------
template<int C, bool PRELU>
__global__ void __launch_bounds__(256) agg_k(
    const float* __restrict__ h, const int* __restrict__ src,
    const float* __restrict__ ew, const int* __restrict__ off,
    const int* __restrict__ perm, const float* __restrict__ bias,
    const float* __restrict__ alpha, float* __restrict__ out, int n)
{
    int node = blockIdx.x * 8 + (threadIdx.x >> 5);
    int lane = threadIdx.x & 31;
    if (node >= n) return;
    int s0 = __ldg(off + node), s1 = __ldg(off + node + 1);
    constexpr int V = C / 128;
    float4 acc[V];
    #pragma unroll
    for (int i = 0; i < V; i++)
        acc[i] = *reinterpret_cast<const float4*>(&bias[(lane + i * 32) * 4]);

    const float4* h4 = reinterpret_cast<const float4*>(h);
    int e = s0;
    for (; e + 1 < s1; e += 2) {           // 2-way unroll for MLP
        int e0 = __ldg(perm + e), e1 = __ldg(perm + e + 1);
        int sa = __ldg(src + e0), sb = __ldg(src + e1);
        float wa = __ldg(ew + e0), wb = __ldg(ew + e1);
        float4 va[V], vb[V];
        #pragma unroll
        for (int i = 0; i < V; i++) {
            va[i] = __ldg(h4 + (size_t)sa * (C / 4) + lane + i * 32);
            vb[i] = __ldg(h4 + (size_t)sb * (C / 4) + lane + i * 32);
        }
        #pragma unroll
        for (int i = 0; i < V; i++) {
            acc[i].x += wa * va[i].x + wb * vb[i].x;
            acc[i].y += wa * va[i].y + wb * vb[i].y;
            acc[i].z += wa * va[i].z + wb * vb[i].z;
            acc[i].w += wa * va[i].w + wb * vb[i].w;
        }
    }
    if (e < s1) {
        int e0 = __ldg(perm + e);
        int sa = __ldg(src + e0);
        float wa = __ldg(ew + e0);
        #pragma unroll
        for (int i = 0; i < V; i++) {
            float4 v = __ldg(h4 + (size_t)sa * (C / 4) + lane + i * 32);
            acc[i].x += wa * v.x; acc[i].y += wa * v.y;
            acc[i].z += wa * v.z; acc[i].w += wa * v.w;
        }
    }
    if (PRELU) {
        float al = alpha[0];
        #pragma unroll
        for (int i = 0; i < V; i++) {
            acc[i].x = (acc[i].x >= 0.f) ? acc[i].x : al * acc[i].x;
            acc[i].y = (acc[i].y >= 0.f) ? acc[i].y : al * acc[i].y;
            acc[i].z = (acc[i].z >= 0.f) ? acc[i].z : al * acc[i].z;
            acc[i].w = (acc[i].w >= 0.f) ? acc[i].w : al * acc[i].w;
        }
    }
    #pragma unroll
    for (int i = 0; i < V; i++)
        *reinterpret_cast<float4*>(&out[(size_t)node * C + (lane + i * 32) * 4]) = acc[i];
}

// ---------------- weight split prep: W[K][N] f32 -> hi/lo packed [N][K/2] ----------------
__global__ void split_w_k(const float* __restrict__ W, uint32_t* __restrict__ hi,
                          uint32_t* __restrict__ lo, int Kp, int N)
{
    int idx = blockIdx.x * blockDim.x + threadIdx.x;
    if (idx >= N * Kp) return;
    int n = idx / Kp, kp = idx % Kp;
    float v0 = W[(size_t)(2 * kp) * N + n];
    float v1 = W[(size_t)(2 * kp + 1) * N + n];
    float h0 = __bfloat162float(__float2bfloat16(v0));
    float h1 = __bfloat162float(__float2bfloat16(v1));
    hi[idx] = pk2(h0, h1);
    lo[idx] = pk2(v0 - h0, v1 - h1);
}

// ---------------- fused fold: PA = Wfc2@Wfc3top@Wfc4, PB = Wfc1@Wfc3bot@Wfc4 ----------------
// 6 blocks x 256 thr. Block handles 64 output rows: stage1 T=X@W3p (64x128,K=256),
// stage2 P=T@Wfc4 (64x64,K=128), epilogue writes bf16 hi/lo packed [n][K/2] directly.
__global__ void __launch_bounds__(256) fold_k(
    const float* __restrict__ Wfc1, const float* __restrict__ Wfc2,
    const float* __restrict__ Wfc3, const float* __restrict__ Wfc4,
    uint32_t* __restrict__ PAh, uint32_t* __restrict__ PAl,
    uint32_t* __restrict__ PBh, uint32_t* __restrict__ PBl)
{
    __shared__ float As[16][64];
    __shared__ float Bs[16][128];
    __shared__ float Ts[64][132];

    int b = blockIdx.x;
    const float* X; const float* W3p; uint32_t *oh, *ol; int Kp, rbase;
    if (b < 4) { X = Wfc2 + b * 64 * 256;       W3p = Wfc3;             oh = PAh; ol = PAl; Kp = 128; rbase = b * 64; }
    else       { X = Wfc1 + (b - 4) * 64 * 256; W3p = Wfc3 + 256 * 128; oh = PBh; ol = PBl; Kp = 64;  rbase = (b - 4) * 64; }

    int tid = threadIdx.x, tx = tid & 15, ty = tid >> 4;

    // stage 1: T[64,128] = X[64,256] @ W3p[256,128]
    float acc[4][8] = {};
    for (int k0 = 0; k0 < 256; k0 += 16) {
        { int r = tid >> 2, kc = (tid & 3) * 4;
          float4 v = *reinterpret_cast<const float4*>(&X[r * 256 + k0 + kc]);
          As[kc + 0][r] = v.x; As[kc + 1][r] = v.y; As[kc + 2][r] = v.z; As[kc + 3][r] = v.w; }
        #pragma unroll
        for (int l = 0; l < 2; l++) {
            int idx = tid + l * 256;
            int kk = idx >> 5, c = (idx & 31) * 4;
            *reinterpret_cast<float4*>(&Bs[kk][c]) =
                *reinterpret_cast<const float4*>(&W3p[(k0 + kk) * 128 + c]);
        }
        __syncthreads();
        #pragma unroll
        for (int kk = 0; kk < 16; kk++) {
            float a[4], bb[8];
            #pragma unroll
            for (int i = 0; i < 4; i++) a[i] = As[kk][ty * 4 + i];
            #pragma unroll
            for (int j = 0; j < 8; j++) bb[j] = Bs[kk][tx * 8 + j];
            #pragma unroll
            for (int i = 0; i < 4; i++)
                #pragma unroll
                for (int j = 0; j < 8; j++)
                    acc[i][j] += a[i] * bb[j];
        }
        __syncthreads();
    }
    #pragma unroll
    for (int i = 0; i < 4; i++)
        #pragma unroll
        for (int j = 0; j < 8; j++)
            Ts[ty * 4 + i][tx * 8 + j] = acc[i][j];
    __syncthreads();

    // stage 2: P[64,64] = T @ Wfc4[128,64]; thread owns rows ty*4..+3, cols tx*4..+3
    float p[4][4] = {};
    for (int k = 0; k < 128; k++) {
        float4 bb = *reinterpret_cast<const float4*>(&Wfc4[k * 64 + tx * 4]);
        float a0 = Ts[ty * 4 + 0][k], a1 = Ts[ty * 4 + 1][k];
        float a2 = Ts[ty * 4 + 2][k], a3 = Ts[ty * 4 + 3][k];
        p[0][0] += a0 * bb.x; p[0][1] += a0 * bb.y; p[0][2] += a0 * bb.z; p[0][3] += a0 * bb.w;
        p[1][0] += a1 * bb.x; p[1][1] += a1 * bb.y; p[1][2] += a1 * bb.z; p[1][3] += a1 * bb.w;
        p[2][0] += a2 * bb.x; p[2][1] += a2 * bb.y; p[2][2] += a2 * bb.z; p[2][3] += a2 * bb.w;
        p[3][0] += a3 * bb.x; p[3][1] += a3 * bb.y; p[3][2] += a3 * bb.z; p[3][3] += a3 * bb.w;
    }

    // epilogue: pack row-pairs into bf16 hi/lo [n][K/2]
    #pragma unroll
    for (int i2 = 0; i2 < 2; i2++) {
        int r = ty * 4 + 2 * i2;
        #pragma unroll
        for (int j = 0; j < 4; j++) {
            float v0 = p[2 * i2][j], v1 = p[2 * i2 + 1][j];
            float h0 = __bfloat162float(__float2bfloat16(v0));
            float h1 = __bfloat162float(__float2bfloat16(v1));
            int c = tx * 4 + j;
            int w = c * Kp + (rbase + r) / 2;
            oh[w] = pk2(h0, h1);
            ol[w] = pk2(v0 - h0, v1 - h1);
        }
    }
}

// ---------------- bf16-split tensor-core GEMM (unchanged from R8) ----------------
#define ASTR 20
#define BSTR 20

struct SmemTC {
    __align__(16) uint32_t Ah[128 * ASTR];
    __align__(16) uint32_t Al[128 * ASTR];
    __align__(16) uint32_t B[2][2][64 * BSTR];
};

__device__ __forceinline__ void gemm_bf_seg(
    const float* __restrict__ A, const uint32_t* __restrict__ Bh,
    const uint32_t* __restrict__ Bl, int M, int K,
    int bm, int bn, int tid, SmemTC* sm, float acc[2][4][4],
    bool doPrelu, float aA)
{
    const int lane = tid & 31, warp = tid >> 5;
    const int wm = warp & 3, wn = warp >> 2;
    const int g = lane >> 2, tq = lane & 3;
    const int Kp = K >> 1;
    const int nt = K / 32;

    float4 aS[4];

    auto stageA = [&](int t) {
        #pragma unroll
        for (int l = 0; l < 4; l++) {
            int idx = tid + l * 256;
            int r = idx >> 3, q = idx & 7;
            int row = bm + r;
            float4 v = make_float4(0.f, 0.f, 0.f, 0.f);
            if (row < M)
                v = *reinterpret_cast<const float4*>(&A[(size_t)row * K + t * 32 + q * 4]);
            aS[l] = v;
        }
    };
    auto storeA = [&]() {
        #pragma unroll
        for (int l = 0; l < 4; l++) {
            int idx = tid + l * 256;
            int r = idx >> 3, q = idx & 7;
            float4 v = aS[l];
            if (doPrelu) {
                v.x = (v.x >= 0.f) ? v.x : aA * v.x;
                v.y = (v.y >= 0.f) ? v.y : aA * v.y;
                v.z = (v.z >= 0.f) ? v.z : aA * v.z;
                v.w = (v.w >= 0.f) ? v.w : aA * v.w;
            }
            float hx = __bfloat162float(__float2bfloat16(v.x));
            float hy = __bfloat162float(__float2bfloat16(v.y));
            float hz = __bfloat162float(__float2bfloat16(v.z));
            float hw = __bfloat162float(__float2bfloat16(v.w));
            uint2 hp = make_uint2(pk2(hx, hy), pk2(hz, hw));
            uint2 lp = make_uint2(pk2(v.x - hx, v.y - hy), pk2(v.z - hz, v.w - hw));
            *reinterpret_cast<uint2*>(&sm->Ah[r * ASTR + q * 2]) = hp;
            *reinterpret_cast<uint2*>(&sm->Al[r * ASTR + q * 2]) = lp;
        }
    };
    auto cpB = [&](int t, int buf) {
        int n = tid >> 2;
        int c = (tid & 3) * 4;
        const uint32_t* sh = Bh + (size_t)(bn + n) * Kp + t * 16 + c;
        const uint32_t* sl = Bl + (size_t)(bn + n) * Kp + t * 16 + c;
        cp_async16(&sm->B[buf][0][n * BSTR + c], sh);
        cp_async16(&sm->B[buf][1][n * BSTR + c], sl);
        cp_async_commit();
    };

    stageA(0);
    cpB(0, 0);
    storeA();
    cp_async_wait0();
    __syncthreads();

    int buf = 0;
    for (int t = 0; t < nt; t++) {
        bool more = (t + 1 < nt);
        if (more) { stageA(t + 1); cpB(t + 1, buf ^ 1); }

        const uint32_t* aH = sm->Ah + (wm * 32 + g) * ASTR;
        const uint32_t* aL = sm->Al + (wm * 32 + g) * ASTR;
        const uint32_t* bH = sm->B[buf][0] + (wn * 32 + g) * BSTR;
        const uint32_t* bL = sm->B[buf][1] + (wn * 32 + g) * BSTR;

        #pragma unroll
        for (int kk = 0; kk < 2; kk++) {
            int kb = kk * 8;
            uint32_t ah[2][4], alr[2][4];
            #pragma unroll
            for (int im = 0; im < 2; im++) {
                const uint32_t* pH = aH + im * 16 * ASTR;
                const uint32_t* pL = aL + im * 16 * ASTR;
                ah[im][0] = pH[kb + tq];
                ah[im][1] = pH[8 * ASTR + kb + tq];
                ah[im][2] = pH[kb + tq + 4];
                ah[im][3] = pH[8 * ASTR + kb + tq + 4];
                alr[im][0] = pL[kb + tq];
                alr[im][1] = pL[8 * ASTR + kb + tq];
                alr[im][2] = pL[kb + tq + 4];
                alr[im][3] = pL[8 * ASTR + kb + tq + 4];
            }
            uint32_t bh[4][2], blr[4][2];
            #pragma unroll
            for (int jn = 0; jn < 4; jn++) {
                const uint32_t* qH = bH + jn * 8 * BSTR;
                const uint32_t* qL = bL + jn * 8 * BSTR;
                bh[jn][0] = qH[kb + tq];
                bh[jn][1] = qH[kb + tq + 4];
                blr[jn][0] = qL[kb + tq];
                blr[jn][1] = qL[kb + tq + 4];
            }
            #pragma unroll
            for (int im = 0; im < 2; im++)
                #pragma unroll
                for (int jn = 0; jn < 4; jn++) {
                    mma_bf16(acc[im][jn], alr[im][0], alr[im][1], alr[im][2], alr[im][3],
                             bh[jn][0], bh[jn][1]);
                    mma_bf16(acc[im][jn], ah[im][0], ah[im][1], ah[im][2], ah[im][3],
                             blr[jn][0], blr[jn][1]);
                    mma_bf16(acc[im][jn], ah[im][0], ah[im][1], ah[im][2], ah[im][3],
                             bh[jn][0], bh[jn][1]);
                }
        }
        __syncthreads();
        if (more) storeA();
        cp_async_wait0();
        __syncthreads();
        buf ^= 1;
    }
}

__global__ void __launch_bounds__(256, 2)
gemm_bf_k(const float* __restrict__ A, const uint32_t* __restrict__ Bh,
          const uint32_t* __restrict__ Bl, int K,
          const float* __restrict__ A2, const uint32_t* __restrict__ B2h,
          const uint32_t* __restrict__ B2l, int K2,
          float* __restrict__ D, int M, int ldD,
          const float* __restrict__ preluA, const float* __restrict__ alphaOut)
{
    __shared__ SmemTC sm;
    const int tid = threadIdx.x;
    const int bm = blockIdx.y * 128, bn = blockIdx.x * 64;

    float acc[2][4][4] = {};
    const float aA = preluA ? preluA[0] : 0.f;

    gemm_bf_seg(A, Bh, Bl, M, K, bm, bn, tid, &sm, acc, preluA != nullptr, aA);
    if (A2)
        gemm_bf_seg(A2, B2h, B2l, M, K2, bm, bn, tid, &sm, acc, false, 0.f);

    const int lane = tid & 31, warp = tid >> 5;
    const int wm = warp & 3, wn = warp >> 2;
    const int g = lane >> 2, tq = lane & 3;
    const float al = alphaOut ? alphaOut[0] : 0.f;

    #pragma unroll
    for (int im = 0; im < 2; im++)
        #pragma unroll
        for (int jn = 0; jn < 4; jn++) {
            int r0 = bm + wm * 32 + im * 16 + g;
            int c0 = bn + wn * 32 + jn * 8 + 2 * tq;
            float2 v0 = make_float2(acc[im][jn][0], acc[im][jn][1]);
            float2 v1 = make_float2(acc[im][jn][2], acc[im][jn][3]);
            if (alphaOut) {
                v0.x = (v0.x >= 0.f) ? v0.x : al * v0.x;
                v0.y = (v0.y >= 0.f) ? v0.y : al * v0.y;
                v1.x = (v1.x >= 0.f) ? v1.x : al * v1.x;
                v1.y = (v1.y >= 0.f) ? v1.y : al * v1.y;
            }
            if (r0 < M)     *reinterpret_cast<float2*>(&D[(size_t)r0 * ldD + c0]) = v0;
            if (r0 + 8 < M) *reinterpret_cast<float2*>(&D[(size_t)(r0 + 8) * ldD + c0]) = v1;
        }
}

// ---------------- launch ----------------
extern "C" void kernel_launch(void* const* d_in, const int* in_sizes, int n_in,
                              void* d_out, int out_size)
{
    const float* seq  = (const float*)d_in[0];
    const int*   ei   = (const int*)  d_in[1];
    const float* ew   = (const float*)d_in[2];
    const float* W1   = (const float*)d_in[3];
    const float* b1   = (const float*)d_in[4];
    const float* W2   = (const float*)d_in[5];
    const float* b2   = (const float*)d_in[6];
    const float* a1   = (const float*)d_in[7];
    const float* a2   = (const float*)d_in[8];
    const float* a3   = (const float*)d_in[9];
    const float* Wfc1 = (const float*)d_in[10];
    const float* Wfc2 = (const float*)d_in[11];
    const float* Wfc3 = (const float*)d_in[12];
    const float* Wfc4 = (const float*)d_in[13];

    const int N = in_sizes[0] / INC;     // 50000
    const int E = in_sizes[2];           // 800000
    const int* src = ei;
    const int* dst = ei + E;

    float *H1, *A1, *H2;
    int *off, *cnt, *perm, *bsum;
    uint32_t *W1h, *W1l, *W2h, *W2l, *PAh, *PAl, *PBh, *PBl;
    cudaGetSymbolAddress((void**)&H1, g_H1);
    cudaGetSymbolAddress((void**)&A1, g_A1);
    cudaGetSymbolAddress((void**)&H2, g_H2);
    cudaGetSymbolAddress((void**)&off, g_off);
    cudaGetSymbolAddress((void**)&cnt, g_cnt);
    cudaGetSymbolAddress((void**)&perm, g_perm);
    cudaGetSymbolAddress((void**)&bsum, g_bsum);
    cudaGetSymbolAddress((void**)&W1h, g_W1h);
    cudaGetSymbolAddress((void**)&W1l, g_W1l);
    cudaGetSymbolAddress((void**)&W2h, g_W2h);
    cudaGetSymbolAddress((void**)&W2l, g_W2l);
    cudaGetSymbolAddress((void**)&PAh, g_PAh);
    cudaGetSymbolAddress((void**)&PAl, g_PAl);
    cudaGetSymbolAddress((void**)&PBh, g_PBh);
    cudaGetSymbolAddress((void**)&PBl, g_PBl);

    float* outx = (float*)d_out;                      // x:     [N,128]
    float* outf = (float*)d_out + (size_t)N * HC;     // feat1: [N,64]

    const dim3 blk(256);
    const int gy = (N + 127) / 128;                   // 391
    const int nb = (N + 255) / 256;                   // 196

    // ---- CSR build (dst-sorted edge permutation) ----
    zero_cnt_k<<<nb, blk>>>(cnt, N);
    hist_k<<<(E + 255) / 256, blk>>>(dst, cnt, E);
    scan1_k<<<nb, blk>>>(cnt, off, bsum, N);
    scan2_k<<<1, blk>>>(bsum, nb);
    scan3_k<<<nb, blk>>>(off, bsum, cnt, N, E);
    fill_k<<<(E + 255) / 256, blk>>>(dst, cnt, perm, E);

    // ---- weight prep: splits + fused FC-head fold (writes PA/PB pre-split) ----
    split_w_k<<<(2*HC * INC/2 + 255) / 256, blk>>>(W1, W1h, W1l, INC/2, 2*HC);
    split_w_k<<<(HC * 2*HC/2 + 255) / 256, blk>>>(W2, W2h, W2l, 2*HC/2, HC);
    fold_k<<<6, blk>>>(Wfc1, Wfc2, Wfc3, Wfc4, PAh, PAl, PBh, PBl);

    // ---- GCN layer 1 ----
    gemm_bf_k<<<dim3(4, gy), blk>>>(seq, W1h, W1l, INC,
                                    nullptr, nullptr, nullptr, 0,
                                    H1, N, 2*HC, nullptr, nullptr);
    agg_k<2*HC, false><<<(N + 7) / 8, blk>>>(H1, src, ew, off, perm, b1, nullptr, A1, N);

    // ---- GCN layer 2 (PReLU a1 fused into GEMM A-load; a2 fused into agg epilogue) ----
    gemm_bf_k<<<dim3(2, gy), blk>>>(A1, W2h, W2l, 2*HC,
                                    nullptr, nullptr, nullptr, 0,
                                    H2, N, HC, a1, nullptr);
    agg_k<HC, true><<<(N + 7) / 8, blk>>>(H2, src, ew, off, perm, b2, a2, outx, N);

    // ---- fused head: feat1 = prelu(seq@PA + x@PB, a3) ----
    gemm_bf_k<<<dim3(1, gy), blk>>>(seq, PAh, PAl, INC,
                                    outx, PBh, PBl, HC,
                                    outf, N, OUTC, nullptr, a3);
}

// round 10
// speedup vs baseline: 3.8733x; 1.0185x over previous
#include <cuda_runtime.h>
#include <cuda_bf16.h>
#include <cstdint>

#define NNODES 50000
#define EMAX   800000
#define INC    256
#define HC     128
#define OUTC   64

// ---------------- scratch (static __device__ — no allocations) ----------------
__device__ float g_H1[NNODES * 2 * HC];   // seq@W1            [N,256]
__device__ float g_A1[NNODES * 2 * HC];   // agg1 (pre-act)    [N,256]
__device__ float g_H2[NNODES * HC];       // prelu(A1)@W2      [N,128]

// CSR build state
__device__ int   g_off[NNODES + 1];
__device__ int   g_cnt[NNODES];           // histogram, then fill cursor
__device__ int   g_srcS[EMAX];            // dst-sorted src indices
__device__ float g_ewS[EMAX];             // dst-sorted edge weights
__device__ int   g_bsum[256];

// packed bf16x2 weight splits: layout [n][K/2]
__device__ uint32_t g_W1h[2*HC * INC/2], g_W1l[2*HC * INC/2];
__device__ uint32_t g_W2h[HC * 2*HC/2],  g_W2l[HC * 2*HC/2];
__device__ uint32_t g_PAh[OUTC * INC/2], g_PAl[OUTC * INC/2];
__device__ uint32_t g_PBh[OUTC * HC/2],  g_PBl[OUTC * HC/2];

// ---------------- small helpers ----------------
__device__ __forceinline__ void cp_async16(void* smem_dst, const void* gmem_src) {
    uint32_t s = (uint32_t)__cvta_generic_to_shared(smem_dst);
    asm volatile("cp.async.cg.shared.global [%0], [%1], 16;\n" :: "r"(s), "l"(gmem_src));
}
__device__ __forceinline__ void cp_async_commit() {
    asm volatile("cp.async.commit_group;\n" ::: "memory");
}
__device__ __forceinline__ void cp_async_wait0() {
    asm volatile("cp.async.wait_group 0;\n" ::: "memory");
}
__device__ __forceinline__ uint32_t pk2(float e, float o) {   // e->low16, o->high16
    __nv_bfloat162 p = __floats2bfloat162_rn(e, o);
    return *reinterpret_cast<uint32_t*>(&p);
}
__device__ __forceinline__ void mma_bf16(float d[4],
    uint32_t a0, uint32_t a1, uint32_t a2, uint32_t a3, uint32_t b0, uint32_t b1)
{
    asm volatile(
        "mma.sync.aligned.m16n8k16.row.col.f32.bf16.bf16.f32 "
        "{%0,%1,%2,%3}, {%4,%5,%6,%7}, {%8,%9}, {%0,%1,%2,%3};\n"
        : "+f"(d[0]), "+f"(d[1]), "+f"(d[2]), "+f"(d[3])
        : "r"(a0), "r"(a1), "r"(a2), "r"(a3), "r"(b0), "r"(b1));
}

// ---------------- CSR build ----------------
__global__ void zero_cnt_k(int* __restrict__ cnt, int n) {
    int i = blockIdx.x * blockDim.x + threadIdx.x;
    if (i < n) cnt[i] = 0;
}
__global__ void hist_k(const int* __restrict__ dst, int* __restrict__ cnt, int E) {
    int e = blockIdx.x * blockDim.x + threadIdx.x;
    if (e < E) atomicAdd(&cnt[dst[e]], 1);
}
__global__ void scan1_k(const int* __restrict__ cnt, int* __restrict__ off,
                        int* __restrict__ bsum, int n)
{
    __shared__ int s[256];
    int tid = threadIdx.x;
    int i = blockIdx.x * 256 + tid;
    int v = (i < n) ? cnt[i] : 0;
    s[tid] = v; __syncthreads();
    #pragma unroll
    for (int d = 1; d < 256; d <<= 1) {
        int t = (tid >= d) ? s[tid - d] : 0;
        __syncthreads();
        s[tid] += t;
        __syncthreads();
    }
    if (i < n) off[i] = s[tid] - v;        // exclusive within block
    if (tid == 255) bsum[blockIdx.x] = s[255];
}
__global__ void scan2_k(int* __restrict__ bsum, int nb)
{
    __shared__ int s[256];
    int tid = threadIdx.x;
    int v = (tid < nb) ? bsum[tid] : 0;
    s[tid] = v; __syncthreads();
    #pragma unroll
    for (int d = 1; d < 256; d <<= 1) {
        int t = (tid >= d) ? s[tid - d] : 0;
        __syncthreads();
        s[tid] += t;
        __syncthreads();
    }
    if (tid < nb) bsum[tid] = s[tid] - v;  // exclusive
}
__global__ void scan3_k(int* __restrict__ off, const int* __restrict__ bsum,
                        int* __restrict__ cnt, int n, int E)
{
    int i = blockIdx.x * blockDim.x + threadIdx.x;
    if (i < n) {
        int o = off[i] + bsum[i >> 8];
        off[i] = o;
        cnt[i] = o;                        // fill cursor
    }
    if (i == 0) off[n] = E;
}
// fill writes the dst-sorted src/weight arrays directly (no perm indirection)
__global__ void fill_k(const int* __restrict__ dst, const int* __restrict__ src,
                       const float* __restrict__ ew, int* __restrict__ cnt,
                       int* __restrict__ srcS, float* __restrict__ ewS, int E)
{
    int e = blockIdx.x * blockDim.x + threadIdx.x;
    if (e < E) {
        int p = atomicAdd(&cnt[dst[e]], 1);
        srcS[p] = src[e];
        ewS[p]  = ew[e];
    }
}

// ---------------- CSR aggregation: out[n] = (bias + sum ew*h[src]) [prelu] ----------------
template<int C, bool PRELU>
__global__ void __launch_bounds__(256) agg_k(
    const float* __restrict__ h, const int* __restrict__ srcS,
    const float* __restrict__ ewS, const int* __restrict__ off,
    const float* __restrict__ bias, const float* __restrict__ alpha,
    float* __restrict__ out, int n)
{
    int node = blockIdx.x * 8 + (threadIdx.x >> 5);
    int lane = threadIdx.x & 31;
    if (node >= n) return;
    int s0 = __ldg(off + node), s1 = __ldg(off + node + 1);
    constexpr int V = C / 128;
    float4 acc[V];
    #pragma unroll
    for (int i = 0; i < V; i++)
        acc[i] = *reinterpret_cast<const float4*>(&bias[(lane + i * 32) * 4]);

    const float4* h4 = reinterpret_cast<const float4*>(h);
    int e = s0;
    for (; e + 4 <= s1; e += 4) {          // 4-edge chunk: batch the latency chains
        int sa = __ldg(srcS + e),     sb = __ldg(srcS + e + 1);
        int sc = __ldg(srcS + e + 2), sd = __ldg(srcS + e + 3);
        float wa = __ldg(ewS + e),     wb = __ldg(ewS + e + 1);
        float wc = __ldg(ewS + e + 2), wd = __ldg(ewS + e + 3);
        float4 va[V], vb[V], vc[V], vd[V];
        #pragma unroll
        for (int i = 0; i < V; i++) {
            va[i] = __ldg(h4 + (size_t)sa * (C / 4) + lane + i * 32);
            vb[i] = __ldg(h4 + (size_t)sb * (C / 4) + lane + i * 32);
            vc[i] = __ldg(h4 + (size_t)sc * (C / 4) + lane + i * 32);
            vd[i] = __ldg(h4 + (size_t)sd * (C / 4) + lane + i * 32);
        }
        #pragma unroll
        for (int i = 0; i < V; i++) {
            acc[i].x += wa * va[i].x + wb * vb[i].x + wc * vc[i].x + wd * vd[i].x;
            acc[i].y += wa * va[i].y + wb * vb[i].y + wc * vc[i].y + wd * vd[i].y;
            acc[i].z += wa * va[i].z + wb * vb[i].z + wc * vc[i].z + wd * vd[i].z;
            acc[i].w += wa * va[i].w + wb * vb[i].w + wc * vc[i].w + wd * vd[i].w;
        }
    }
    for (; e < s1; e++) {
        int sa = __ldg(srcS + e);
        float wa = __ldg(ewS + e);
        #pragma unroll
        for (int i = 0; i < V; i++) {
            float4 v = __ldg(h4 + (size_t)sa * (C / 4) + lane + i * 32);
            acc[i].x += wa * v.x; acc[i].y += wa * v.y;
            acc[i].z += wa * v.z; acc[i].w += wa * v.w;
        }
    }
    if (PRELU) {
        float al = alpha[0];
        #pragma unroll
        for (int i = 0; i < V; i++) {
            acc[i].x = (acc[i].x >= 0.f) ? acc[i].x : al * acc[i].x;
            acc[i].y = (acc[i].y >= 0.f) ? acc[i].y : al * acc[i].y;
            acc[i].z = (acc[i].z >= 0.f) ? acc[i].z : al * acc[i].z;
            acc[i].w = (acc[i].w >= 0.f) ? acc[i].w : al * acc[i].w;
        }
    }
    #pragma unroll
    for (int i = 0; i < V; i++)
        *reinterpret_cast<float4*>(&out[(size_t)node * C + (lane + i * 32) * 4]) = acc[i];
}

// ---------------- combined weight split: W1 and W2 in one launch ----------------
__device__ __forceinline__ void split_one(const float* __restrict__ W,
    uint32_t* __restrict__ hi, uint32_t* __restrict__ lo, int Kp, int N, int idx)
{
    int n = idx / Kp, kp = idx % Kp;
    float v0 = W[(size_t)(2 * kp) * N + n];
    float v1 = W[(size_t)(2 * kp + 1) * N + n];
    float h0 = __bfloat162float(__float2bfloat16(v0));
    float h1 = __bfloat162float(__float2bfloat16(v1));
    hi[idx] = pk2(h0, h1);
    lo[idx] = pk2(v0 - h0, v1 - h1);
}
__global__ void splitw2_k(const float* __restrict__ W1, uint32_t* __restrict__ W1h,
                          uint32_t* __restrict__ W1l,
                          const float* __restrict__ W2, uint32_t* __restrict__ W2h,
                          uint32_t* __restrict__ W2l)
{
    int idx = blockIdx.x * blockDim.x + threadIdx.x;
    const int n1 = 2*HC * INC/2;           // 32768
    const int n2 = HC * 2*HC/2;            // 16384
    if (idx < n1)            split_one(W1, W1h, W1l, INC/2, 2*HC, idx);
    else if (idx < n1 + n2)  split_one(W2, W2h, W2l, 2*HC/2, HC, idx - n1);
}

// ---------------- fused fold: PA = Wfc2@Wfc3top@Wfc4, PB = Wfc1@Wfc3bot@Wfc4 ----------------
__global__ void __launch_bounds__(256) fold_k(
    const float* __restrict__ Wfc1, const float* __restrict__ Wfc2,
    const float* __restrict__ Wfc3, const float* __restrict__ Wfc4,
    uint32_t* __restrict__ PAh, uint32_t* __restrict__ PAl,
    uint32_t* __restrict__ PBh, uint32_t* __restrict__ PBl)
{
    __shared__ float As[16][64];
    __shared__ float Bs[16][128];
    __shared__ float Ts[64][132];

    int b = blockIdx.x;
    const float* X; const float* W3p; uint32_t *oh, *ol; int Kp, rbase;
    if (b < 4) { X = Wfc2 + b * 64 * 256;       W3p = Wfc3;             oh = PAh; ol = PAl; Kp = 128; rbase = b * 64; }
    else       { X = Wfc1 + (b - 4) * 64 * 256; W3p = Wfc3 + 256 * 128; oh = PBh; ol = PBl; Kp = 64;  rbase = (b - 4) * 64; }

    int tid = threadIdx.x, tx = tid & 15, ty = tid >> 4;

    float acc[4][8] = {};
    for (int k0 = 0; k0 < 256; k0 += 16) {
        { int r = tid >> 2, kc = (tid & 3) * 4;
          float4 v = *reinterpret_cast<const float4*>(&X[r * 256 + k0 + kc]);
          As[kc + 0][r] = v.x; As[kc + 1][r] = v.y; As[kc + 2][r] = v.z; As[kc + 3][r] = v.w; }
        #pragma unroll
        for (int l = 0; l < 2; l++) {
            int idx = tid + l * 256;
            int kk = idx >> 5, c = (idx & 31) * 4;
            *reinterpret_cast<float4*>(&Bs[kk][c]) =
                *reinterpret_cast<const float4*>(&W3p[(k0 + kk) * 128 + c]);
        }
        __syncthreads();
        #pragma unroll
        for (int kk = 0; kk < 16; kk++) {
            float a[4], bb[8];
            #pragma unroll
            for (int i = 0; i < 4; i++) a[i] = As[kk][ty * 4 + i];
            #pragma unroll
            for (int j = 0; j < 8; j++) bb[j] = Bs[kk][tx * 8 + j];
            #pragma unroll
            for (int i = 0; i < 4; i++)
                #pragma unroll
                for (int j = 0; j < 8; j++)
                    acc[i][j] += a[i] * bb[j];
        }
        __syncthreads();
    }
    #pragma unroll
    for (int i = 0; i < 4; i++)
        #pragma unroll
        for (int j = 0; j < 8; j++)
            Ts[ty * 4 + i][tx * 8 + j] = acc[i][j];
    __syncthreads();

    float p[4][4] = {};
    for (int k = 0; k < 128; k++) {
        float4 bb = *reinterpret_cast<const float4*>(&Wfc4[k * 64 + tx * 4]);
        float a0 = Ts[ty * 4 + 0][k], a1 = Ts[ty * 4 + 1][k];
        float a2 = Ts[ty * 4 + 2][k], a3 = Ts[ty * 4 + 3][k];
        p[0][0] += a0 * bb.x; p[0][1] += a0 * bb.y; p[0][2] += a0 * bb.z; p[0][3] += a0 * bb.w;
        p[1][0] += a1 * bb.x; p[1][1] += a1 * bb.y; p[1][2] += a1 * bb.z; p[1][3] += a1 * bb.w;
        p[2][0] += a2 * bb.x; p[2][1] += a2 * bb.y; p[2][2] += a2 * bb.z; p[2][3] += a2 * bb.w;
        p[3][0] += a3 * bb.x; p[3][1] += a3 * bb.y; p[3][2] += a3 * bb.z; p[3][3] += a3 * bb.w;
    }

    #pragma unroll
    for (int i2 = 0; i2 < 2; i2++) {
        int r = ty * 4 + 2 * i2;
        #pragma unroll
        for (int j = 0; j < 4; j++) {
            float v0 = p[2 * i2][j], v1 = p[2 * i2 + 1][j];
            float h0 = __bfloat162float(__float2bfloat16(v0));
            float h1 = __bfloat162float(__float2bfloat16(v1));
            int c = tx * 4 + j;
            int w = c * Kp + (rbase + r) / 2;
            oh[w] = pk2(h0, h1);
            ol[w] = pk2(v0 - h0, v1 - h1);
        }
    }
}

// ---------------- bf16-split tensor-core GEMM (unchanged from R8/R9) ----------------
#define ASTR 20
#define BSTR 20

struct SmemTC {
    __align__(16) uint32_t Ah[128 * ASTR];
    __align__(16) uint32_t Al[128 * ASTR];
    __align__(16) uint32_t B[2][2][64 * BSTR];
};

__device__ __forceinline__ void gemm_bf_seg(
    const float* __restrict__ A, const uint32_t* __restrict__ Bh,
    const uint32_t* __restrict__ Bl, int M, int K,
    int bm, int bn, int tid, SmemTC* sm, float acc[2][4][4],
    bool doPrelu, float aA)
{
    const int lane = tid & 31, warp = tid >> 5;
    const int wm = warp & 3, wn = warp >> 2;
    const int g = lane >> 2, tq = lane & 3;
    const int Kp = K >> 1;
    const int nt = K / 32;

    float4 aS[4];

    auto stageA = [&](int t) {
        #pragma unroll
        for (int l = 0; l < 4; l++) {
            int idx = tid + l * 256;
            int r = idx >> 3, q = idx & 7;
            int row = bm + r;
            float4 v = make_float4(0.f, 0.f, 0.f, 0.f);
            if (row < M)
                v = *reinterpret_cast<const float4*>(&A[(size_t)row * K + t * 32 + q * 4]);
            aS[l] = v;
        }
    };
    auto storeA = [&]() {
        #pragma unroll
        for (int l = 0; l < 4; l++) {
            int idx = tid + l * 256;
            int r = idx >> 3, q = idx & 7;
            float4 v = aS[l];
            if (doPrelu) {
                v.x = (v.x >= 0.f) ? v.x : aA * v.x;
                v.y = (v.y >= 0.f) ? v.y : aA * v.y;
                v.z = (v.z >= 0.f) ? v.z : aA * v.z;
                v.w = (v.w >= 0.f) ? v.w : aA * v.w;
            }
            float hx = __bfloat162float(__float2bfloat16(v.x));
            float hy = __bfloat162float(__float2bfloat16(v.y));
            float hz = __bfloat162float(__float2bfloat16(v.z));
            float hw = __bfloat162float(__float2bfloat16(v.w));
            uint2 hp = make_uint2(pk2(hx, hy), pk2(hz, hw));
            uint2 lp = make_uint2(pk2(v.x - hx, v.y - hy), pk2(v.z - hz, v.w - hw));
            *reinterpret_cast<uint2*>(&sm->Ah[r * ASTR + q * 2]) = hp;
            *reinterpret_cast<uint2*>(&sm->Al[r * ASTR + q * 2]) = lp;
        }
    };
    auto cpB = [&](int t, int buf) {
        int n = tid >> 2;
        int c = (tid & 3) * 4;
        const uint32_t* sh = Bh + (size_t)(bn + n) * Kp + t * 16 + c;
        const uint32_t* sl = Bl + (size_t)(bn + n) * Kp + t * 16 + c;
        cp_async16(&sm->B[buf][0][n * BSTR + c], sh);
        cp_async16(&sm->B[buf][1][n * BSTR + c], sl);
        cp_async_commit();
    };

    stageA(0);
    cpB(0, 0);
    storeA();
    cp_async_wait0();
    __syncthreads();

    int buf = 0;
    for (int t = 0; t < nt; t++) {
        bool more = (t + 1 < nt);
        if (more) { stageA(t + 1); cpB(t + 1, buf ^ 1); }

        const uint32_t* aH = sm->Ah + (wm * 32 + g) * ASTR;
        const uint32_t* aL = sm->Al + (wm * 32 + g) * ASTR;
        const uint32_t* bH = sm->B[buf][0] + (wn * 32 + g) * BSTR;
        const uint32_t* bL = sm->B[buf][1] + (wn * 32 + g) * BSTR;

        #pragma unroll
        for (int kk = 0; kk < 2; kk++) {
            int kb = kk * 8;
            uint32_t ah[2][4], alr[2][4];
            #pragma unroll
            for (int im = 0; im < 2; im++) {
                const uint32_t* pH = aH + im * 16 * ASTR;
                const uint32_t* pL = aL + im * 16 * ASTR;
                ah[im][0] = pH[kb + tq];
                ah[im][1] = pH[8 * ASTR + kb + tq];
                ah[im][2] = pH[kb + tq + 4];
                ah[im][3] = pH[8 * ASTR + kb + tq + 4];
                alr[im][0] = pL[kb + tq];
                alr[im][1] = pL[8 * ASTR + kb + tq];
                alr[im][2] = pL[kb + tq + 4];
                alr[im][3] = pL[8 * ASTR + kb + tq + 4];
            }
            uint32_t bh[4][2], blr[4][2];
            #pragma unroll
            for (int jn = 0; jn < 4; jn++) {
                const uint32_t* qH = bH + jn * 8 * BSTR;
                const uint32_t* qL = bL + jn * 8 * BSTR;
                bh[jn][0] = qH[kb + tq];
                bh[jn][1] = qH[kb + tq + 4];
                blr[jn][0] = qL[kb + tq];
                blr[jn][1] = qL[kb + tq + 4];
            }
            #pragma unroll
            for (int im = 0; im < 2; im++)
                #pragma unroll
                for (int jn = 0; jn < 4; jn++) {
                    mma_bf16(acc[im][jn], alr[im][0], alr[im][1], alr[im][2], alr[im][3],
                             bh[jn][0], bh[jn][1]);
                    mma_bf16(acc[im][jn], ah[im][0], ah[im][1], ah[im][2], ah[im][3],
                             blr[jn][0], blr[jn][1]);
                    mma_bf16(acc[im][jn], ah[im][0], ah[im][1], ah[im][2], ah[im][3],
                             bh[jn][0], bh[jn][1]);
                }
        }
        __syncthreads();
        if (more) storeA();
        cp_async_wait0();
        __syncthreads();
        buf ^= 1;
    }
}

__global__ void __launch_bounds__(256, 2)
gemm_bf_k(const float* __restrict__ A, const uint32_t* __restrict__ Bh,
          const uint32_t* __restrict__ Bl, int K,
          const float* __restrict__ A2, const uint32_t* __restrict__ B2h,
          const uint32_t* __restrict__ B2l, int K2,
          float* __restrict__ D, int M, int ldD,
          const float* __restrict__ preluA, const float* __restrict__ alphaOut)
{
    __shared__ SmemTC sm;
    const int tid = threadIdx.x;
    const int bm = blockIdx.y * 128, bn = blockIdx.x * 64;

    float acc[2][4][4] = {};
    const float aA = preluA ? preluA[0] : 0.f;

    gemm_bf_seg(A, Bh, Bl, M, K, bm, bn, tid, &sm, acc, preluA != nullptr, aA);
    if (A2)
        gemm_bf_seg(A2, B2h, B2l, M, K2, bm, bn, tid, &sm, acc, false, 0.f);

    const int lane = tid & 31, warp = tid >> 5;
    const int wm = warp & 3, wn = warp >> 2;
    const int g = lane >> 2, tq = lane & 3;
    const float al = alphaOut ? alphaOut[0] : 0.f;

    #pragma unroll
    for (int im = 0; im < 2; im++)
        #pragma unroll
        for (int jn = 0; jn < 4; jn++) {
            int r0 = bm + wm * 32 + im * 16 + g;
            int c0 = bn + wn * 32 + jn * 8 + 2 * tq;
            float2 v0 = make_float2(acc[im][jn][0], acc[im][jn][1]);
            float2 v1 = make_float2(acc[im][jn][2], acc[im][jn][3]);
            if (alphaOut) {
                v0.x = (v0.x >= 0.f) ? v0.x : al * v0.x;
                v0.y = (v0.y >= 0.f) ? v0.y : al * v0.y;
                v1.x = (v1.x >= 0.f) ? v1.x : al * v1.x;
                v1.y = (v1.y >= 0.f) ? v1.y : al * v1.y;
            }
            if (r0 < M)     *reinterpret_cast<float2*>(&D[(size_t)r0 * ldD + c0]) = v0;
            if (r0 + 8 < M) *reinterpret_cast<float2*>(&D[(size_t)(r0 + 8) * ldD + c0]) = v1;
        }
}

// ---------------- launch ----------------
extern "C" void kernel_launch(void* const* d_in, const int* in_sizes, int n_in,
                              void* d_out, int out_size)
{
    const float* seq  = (const float*)d_in[0];
    const int*   ei   = (const int*)  d_in[1];
    const float* ew   = (const float*)d_in[2];
    const float* W1   = (const float*)d_in[3];
    const float* b1   = (const float*)d_in[4];
    const float* W2   = (const float*)d_in[5];
    const float* b2   = (const float*)d_in[6];
    const float* a1   = (const float*)d_in[7];
    const float* a2   = (const float*)d_in[8];
    const float* a3   = (const float*)d_in[9];
    const float* Wfc1 = (const float*)d_in[10];
    const float* Wfc2 = (const float*)d_in[11];
    const float* Wfc3 = (const float*)d_in[12];
    const float* Wfc4 = (const float*)d_in[13];

    const int N = in_sizes[0] / INC;     // 50000
    const int E = in_sizes[2];           // 800000
    const int* src = ei;
    const int* dst = ei + E;

    float *H1, *A1, *H2, *ewS;
    int *off, *cnt, *srcS, *bsum;
    uint32_t *W1h, *W1l, *W2h, *W2l, *PAh, *PAl, *PBh, *PBl;
    cudaGetSymbolAddress((void**)&H1, g_H1);
    cudaGetSymbolAddress((void**)&A1, g_A1);
    cudaGetSymbolAddress((void**)&H2, g_H2);
    cudaGetSymbolAddress((void**)&off, g_off);
    cudaGetSymbolAddress((void**)&cnt, g_cnt);
    cudaGetSymbolAddress((void**)&srcS, g_srcS);
    cudaGetSymbolAddress((void**)&ewS, g_ewS);
    cudaGetSymbolAddress((void**)&bsum, g_bsum);
    cudaGetSymbolAddress((void**)&W1h, g_W1h);
    cudaGetSymbolAddress((void**)&W1l, g_W1l);
    cudaGetSymbolAddress((void**)&W2h, g_W2h);
    cudaGetSymbolAddress((void**)&W2l, g_W2l);
    cudaGetSymbolAddress((void**)&PAh, g_PAh);
    cudaGetSymbolAddress((void**)&PAl, g_PAl);
    cudaGetSymbolAddress((void**)&PBh, g_PBh);
    cudaGetSymbolAddress((void**)&PBl, g_PBl);

    float* outx = (float*)d_out;                      // x:     [N,128]
    float* outf = (float*)d_out + (size_t)N * HC;     // feat1: [N,64]

    const dim3 blk(256);
    const int gy = (N + 127) / 128;                   // 391
    const int nb = (N + 255) / 256;                   // 196

    // ---- CSR build (dst-sorted src/weight arrays) ----
    zero_cnt_k<<<nb, blk>>>(cnt, N);
    hist_k<<<(E + 255) / 256, blk>>>(dst, cnt, E);
    scan1_k<<<nb, blk>>>(cnt, off, bsum, N);
    scan2_k<<<1, blk>>>(bsum, nb);
    scan3_k<<<nb, blk>>>(off, bsum, cnt, N, E);
    fill_k<<<(E + 255) / 256, blk>>>(dst, src, ew, cnt, srcS, ewS, E);

    // ---- weight prep: combined splits + fused FC-head fold ----
    splitw2_k<<<(2*HC*INC/2 + HC*HC + 255) / 256, blk>>>(W1, W1h, W1l, W2, W2h, W2l);
    fold_k<<<6, blk>>>(Wfc1, Wfc2, Wfc3, Wfc4, PAh, PAl, PBh, PBl);

    // ---- GCN layer 1 ----
    gemm_bf_k<<<dim3(4, gy), blk>>>(seq, W1h, W1l, INC,
                                    nullptr, nullptr, nullptr, 0,
                                    H1, N, 2*HC, nullptr, nullptr);
    agg_k<2*HC, false><<<(N + 7) / 8, blk>>>(H1, srcS, ewS, off, b1, nullptr, A1, N);

    // ---- GCN layer 2 (PReLU a1 fused into GEMM A-load; a2 fused into agg epilogue) ----
    gemm_bf_k<<<dim3(2, gy), blk>>>(A1, W2h, W2l, 2*HC,
                                    nullptr, nullptr, nullptr, 0,
                                    H2, N, HC, a1, nullptr);
    agg_k<HC, true><<<(N + 7) / 8, blk>>>(H2, srcS, ewS, off, b2, a2, outx, N);

    // ---- fused head: feat1 = prelu(seq@PA + x@PB, a3) ----
    gemm_bf_k<<<dim3(1, gy), blk>>>(seq, PAh, PAl, INC,
                                    outx, PBh, PBl, HC,
                                    outf, N, OUTC, nullptr, a3);
}

// round 13
// speedup vs baseline: 4.2213x; 1.0898x over previous
#include <cuda_runtime.h>
#include <cuda_bf16.h>
#include <cuda_fp16.h>
#include <cstdint>

#define NNODES 50000
#define EMAX   800000
#define INC    256
#define HC     128
#define OUTC   64

// ---------------- scratch (static __device__ — no allocations) ----------------
__device__ __half g_H1[NNODES * 2 * HC];  // seq@W1 (fp16)     [N,256]
__device__ float  g_A1[NNODES * 2 * HC];  // agg1 (pre-act)    [N,256]
__device__ __half g_H2[NNODES * HC];      // prelu(A1)@W2 fp16 [N,128]

// CSR build state
__device__ int   g_off[NNODES + 1];
__device__ int   g_cnt[NNODES];
__device__ int   g_srcS[EMAX];
__device__ float g_ewS[EMAX];
__device__ int   g_bsum[256];

// packed bf16x2 weight splits: layout [n][K/2]
__device__ uint32_t g_W1h[2*HC * INC/2], g_W1l[2*HC * INC/2];
__device__ uint32_t g_W2h[HC * 2*HC/2],  g_W2l[HC * 2*HC/2];
__device__ uint32_t g_PAh[OUTC * INC/2], g_PAl[OUTC * INC/2];
__device__ uint32_t g_PBh[OUTC * HC/2],  g_PBl[OUTC * HC/2];

// ---------------- small helpers ----------------
__device__ __forceinline__ void cp_async16(void* smem_dst, const void* gmem_src) {
    uint32_t s = (uint32_t)__cvta_generic_to_shared(smem_dst);
    asm volatile("cp.async.cg.shared.global [%0], [%1], 16;\n" :: "r"(s), "l"(gmem_src));
}
__device__ __forceinline__ void cp_async_commit() {
    asm volatile("cp.async.commit_group;\n" ::: "memory");
}
__device__ __forceinline__ void cp_async_wait0() {
    asm volatile("cp.async.wait_group 0;\n" ::: "memory");
}
__device__ __forceinline__ uint32_t pk2(float e, float o) {   // e->low16, o->high16
    __nv_bfloat162 p = __floats2bfloat162_rn(e, o);
    return *reinterpret_cast<uint32_t*>(&p);
}
__device__ __forceinline__ void mma_bf16(float d[4],
    uint32_t a0, uint32_t a1, uint32_t a2, uint32_t a3, uint32_t b0, uint32_t b1)
{
    asm volatile(
        "mma.sync.aligned.m16n8k16.row.col.f32.bf16.bf16.f32 "
        "{%0,%1,%2,%3}, {%4,%5,%6,%7}, {%8,%9}, {%0,%1,%2,%3};\n"
        : "+f"(d[0]), "+f"(d[1]), "+f"(d[2]), "+f"(d[3])
        : "r"(a0), "r"(a1), "r"(a2), "r"(a3), "r"(b0), "r"(b1));
}

// ---------------- CSR build ----------------
__global__ void zero_cnt_k(int* __restrict__ cnt, int n) {
    int i = blockIdx.x * blockDim.x + threadIdx.x;
    if (i < n) cnt[i] = 0;
}
__global__ void hist_k(const int* __restrict__ dst, int* __restrict__ cnt, int E) {
    int e = blockIdx.x * blockDim.x + threadIdx.x;
    if (e < E) atomicAdd(&cnt[dst[e]], 1);
}
__global__ void scan1_k(const int* __restrict__ cnt, int* __restrict__ off,
                        int* __restrict__ bsum, int n)
{
    __shared__ int s[256];
    int tid = threadIdx.x;
    int i = blockIdx.x * 256 + tid;
    int v = (i < n) ? cnt[i] : 0;
    s[tid] = v; __syncthreads();
    #pragma unroll
    for (int d = 1; d < 256; d <<= 1) {
        int t = (tid >= d) ? s[tid - d] : 0;
        __syncthreads();
        s[tid] += t;
        __syncthreads();
    }
    if (i < n) off[i] = s[tid] - v;
    if (tid == 255) bsum[blockIdx.x] = s[255];
}
__global__ void scan2_k(int* __restrict__ bsum, int nb)
{
    __shared__ int s[256];
    int tid = threadIdx.x;
    int v = (tid < nb) ? bsum[tid] : 0;
    s[tid] = v; __syncthreads();
    #pragma unroll
    for (int d = 1; d < 256; d <<= 1) {
        int t = (tid >= d) ? s[tid - d] : 0;
        __syncthreads();
        s[tid] += t;
        __syncthreads();
    }
    if (tid < nb) bsum[tid] = s[tid] - v;
}
__global__ void scan3_k(int* __restrict__ off, const int* __restrict__ bsum,
                        int* __restrict__ cnt, int n, int E)
{
    int i = blockIdx.x * blockDim.x + threadIdx.x;
    if (i < n) {
        int o = off[i] + bsum[i >> 8];
        off[i] = o;
        cnt[i] = o;
    }
    if (i == 0) off[n] = E;
}
__global__ void fill_k(const int* __restrict__ dst, const int* __restrict__ src,
                       const float* __restrict__ ew, int* __restrict__ cnt,
                       int* __restrict__ srcS, float* __restrict__ ewS, int E)
{
    int e = blockIdx.x * blockDim.x + threadIdx.x;
    if (e < E) {
        int p = atomicAdd(&cnt[dst[e]], 1);
        srcS[p] = src[e];
        ewS[p]  = ew[e];
    }
}

// ---------------- fp16 unpack-accumulate helpers ----------------
__device__ __forceinline__ void acc8(float* acc, uint4 v, float w) {
    float2 f;
    f = __half22float2(*reinterpret_cast<__half2*>(&v.x)); acc[0] += w * f.x; acc[1] += w * f.y;
    f = __half22float2(*reinterpret_cast<__half2*>(&v.y)); acc[2] += w * f.x; acc[3] += w * f.y;
    f = __half22float2(*reinterpret_cast<__half2*>(&v.z)); acc[4] += w * f.x; acc[5] += w * f.y;
    f = __half22float2(*reinterpret_cast<__half2*>(&v.w)); acc[6] += w * f.x; acc[7] += w * f.y;
}
__device__ __forceinline__ void acc4(float* acc, uint2 v, float w) {
    float2 f;
    f = __half22float2(*reinterpret_cast<__half2*>(&v.x)); acc[0] += w * f.x; acc[1] += w * f.y;
    f = __half22float2(*reinterpret_cast<__half2*>(&v.y)); acc[2] += w * f.x; acc[3] += w * f.y;
}

// ---------------- CSR aggregation over fp16 h: out = (bias + sum ew*h[src]) [prelu] ----------------
template<int C, bool PRELU>
__global__ void __launch_bounds__(256) agg_k(
    const __half* __restrict__ h, const int* __restrict__ srcS,
    const float* __restrict__ ewS, const int* __restrict__ off,
    const float* __restrict__ bias, const float* __restrict__ alpha,
    float* __restrict__ out, int n)
{
    int node = blockIdx.x * 8 + (threadIdx.x >> 5);
    int lane = threadIdx.x & 31;
    if (node >= n) return;
    int s0 = __ldg(off + node), s1 = __ldg(off + node + 1);
    constexpr int F = C / 32;               // halves (=floats) per lane: 8 (C=256) or 4 (C=128)
    float acc[F];
    #pragma unroll
    for (int j = 0; j < F; j += 4) {
        float4 b4 = *reinterpret_cast<const float4*>(&bias[lane * F + j]);
        acc[j] = b4.x; acc[j+1] = b4.y; acc[j+2] = b4.z; acc[j+3] = b4.w;
    }

    int e = s0;
    if constexpr (C == 256) {
        constexpr int RS = C / 8;           // uint4 (8 halves) per row = 32
        const uint4* hv = reinterpret_cast<const uint4*>(h);
        for (; e + 4 <= s1; e += 4) {
            int ss[4]; float ws[4]; uint4 vv[4];
            #pragma unroll
            for (int q = 0; q < 4; q++) { ss[q] = __ldg(srcS + e + q); ws[q] = __ldg(ewS + e + q); }
            #pragma unroll
            for (int q = 0; q < 4; q++) vv[q] = __ldg(hv + (size_t)ss[q] * RS + lane);
            #pragma unroll
            for (int q = 0; q < 4; q++) acc8(acc, vv[q], ws[q]);
        }
        for (; e < s1; e++) {
            int s = __ldg(srcS + e); float w = __ldg(ewS + e);
            acc8(acc, __ldg(hv + (size_t)s * RS + lane), w);
        }
    } else {
        constexpr int RS = C / 4;           // uint2 (4 halves) per row = 32   [R11 bug: was 16]
        const uint2* hv = reinterpret_cast<const uint2*>(h);
        for (; e + 4 <= s1; e += 4) {
            int ss[4]; float ws[4]; uint2 vv[4];
            #pragma unroll
            for (int q = 0; q < 4; q++) { ss[q] = __ldg(srcS + e + q); ws[q] = __ldg(ewS + e + q); }
            #pragma unroll
            for (int q = 0; q < 4; q++) vv[q] = __ldg(hv + (size_t)ss[q] * RS + lane);
            #pragma unroll
            for (int q = 0; q < 4; q++) acc4(acc, vv[q], ws[q]);
        }
        for (; e < s1; e++) {
            int s = __ldg(srcS + e); float w = __ldg(ewS + e);
            acc4(acc, __ldg(hv + (size_t)s * RS + lane), w);
        }
    }

    if (PRELU) {
        float al = alpha[0];
        #pragma unroll
        for (int j = 0; j < F; j++)
            acc[j] = (acc[j] >= 0.f) ? acc[j] : al * acc[j];
    }
    #pragma unroll
    for (int j = 0; j < F; j += 4)
        *reinterpret_cast<float4*>(&out[(size_t)node * C + lane * F + j]) =
            make_float4(acc[j], acc[j+1], acc[j+2], acc[j+3]);
}

// ---------------- combined weight split ----------------
__device__ __forceinline__ void split_one(const float* __restrict__ W,
    uint32_t* __restrict__ hi, uint32_t* __restrict__ lo, int Kp, int N, int idx)
{
    int n = idx / Kp, kp = idx % Kp;
    float v0 = W[(size_t)(2 * kp) * N + n];
    float v1 = W[(size_t)(2 * kp + 1) * N + n];
    float h0 = __bfloat162float(__float2bfloat16(v0));
    float h1 = __bfloat162float(__float2bfloat16(v1));
    hi[idx] = pk2(h0, h1);
    lo[idx] = pk2(v0 - h0, v1 - h1);
}
__global__ void splitw2_k(const float* __restrict__ W1, uint32_t* __restrict__ W1h,
                          uint32_t* __restrict__ W1l,
                          const float* __restrict__ W2, uint32_t* __restrict__ W2h,
                          uint32_t* __restrict__ W2l)
{
    int idx = blockIdx.x * blockDim.x + threadIdx.x;
    const int n1 = 2*HC * INC/2;
    const int n2 = HC * 2*HC/2;
    if (idx < n1)            split_one(W1, W1h, W1l, INC/2, 2*HC, idx);
    else if (idx < n1 + n2)  split_one(W2, W2h, W2l, 2*HC/2, HC, idx - n1);
}

// ---------------- fused fold: PA = Wfc2@Wfc3top@Wfc4, PB = Wfc1@Wfc3bot@Wfc4 ----------------
__global__ void __launch_bounds__(256) fold_k(
    const float* __restrict__ Wfc1, const float* __restrict__ Wfc2,
    const float* __restrict__ Wfc3, const float* __restrict__ Wfc4,
    uint32_t* __restrict__ PAh, uint32_t* __restrict__ PAl,
    uint32_t* __restrict__ PBh, uint32_t* __restrict__ PBl)
{
    __shared__ float As[16][64];
    __shared__ float Bs[16][128];
    __shared__ float Ts[64][132];

    int b = blockIdx.x;
    const float* X; const float* W3p; uint32_t *oh, *ol; int Kp, rbase;
    if (b < 4) { X = Wfc2 + b * 64 * 256;       W3p = Wfc3;             oh = PAh; ol = PAl; Kp = 128; rbase = b * 64; }
    else       { X = Wfc1 + (b - 4) * 64 * 256; W3p = Wfc3 + 256 * 128; oh = PBh; ol = PBl; Kp = 64;  rbase = (b - 4) * 64; }

    int tid = threadIdx.x, tx = tid & 15, ty = tid >> 4;

    float acc[4][8] = {};
    for (int k0 = 0; k0 < 256; k0 += 16) {
        { int r = tid >> 2, kc = (tid & 3) * 4;
          float4 v = *reinterpret_cast<const float4*>(&X[r * 256 + k0 + kc]);
          As[kc + 0][r] = v.x; As[kc + 1][r] = v.y; As[kc + 2][r] = v.z; As[kc + 3][r] = v.w; }
        #pragma unroll
        for (int l = 0; l < 2; l++) {
            int idx = tid + l * 256;
            int kk = idx >> 5, c = (idx & 31) * 4;
            *reinterpret_cast<float4*>(&Bs[kk][c]) =
                *reinterpret_cast<const float4*>(&W3p[(k0 + kk) * 128 + c]);
        }
        __syncthreads();
        #pragma unroll
        for (int kk = 0; kk < 16; kk++) {
            float a[4], bb[8];
            #pragma unroll
            for (int i = 0; i < 4; i++) a[i] = As[kk][ty * 4 + i];
            #pragma unroll
            for (int j = 0; j < 8; j++) bb[j] = Bs[kk][tx * 8 + j];
            #pragma unroll
            for (int i = 0; i < 4; i++)
                #pragma unroll
                for (int j = 0; j < 8; j++)
                    acc[i][j] += a[i] * bb[j];
        }
        __syncthreads();
    }
    #pragma unroll
    for (int i = 0; i < 4; i++)
        #pragma unroll
        for (int j = 0; j < 8; j++)
            Ts[ty * 4 + i][tx * 8 + j] = acc[i][j];
    __syncthreads();

    float p[4][4] = {};
    for (int k = 0; k < 128; k++) {
        float4 bb = *reinterpret_cast<const float4*>(&Wfc4[k * 64 + tx * 4]);
        float a0 = Ts[ty * 4 + 0][k], a1 = Ts[ty * 4 + 1][k];
        float a2 = Ts[ty * 4 + 2][k], a3 = Ts[ty * 4 + 3][k];
        p[0][0] += a0 * bb.x; p[0][1] += a0 * bb.y; p[0][2] += a0 * bb.z; p[0][3] += a0 * bb.w;
        p[1][0] += a1 * bb.x; p[1][1] += a1 * bb.y; p[1][2] += a1 * bb.z; p[1][3] += a1 * bb.w;
        p[2][0] += a2 * bb.x; p[2][1] += a2 * bb.y; p[2][2] += a2 * bb.z; p[2][3] += a2 * bb.w;
        p[3][0] += a3 * bb.x; p[3][1] += a3 * bb.y; p[3][2] += a3 * bb.z; p[3][3] += a3 * bb.w;
    }

    #pragma unroll
    for (int i2 = 0; i2 < 2; i2++) {
        int r = ty * 4 + 2 * i2;
        #pragma unroll
        for (int j = 0; j < 4; j++) {
            float v0 = p[2 * i2][j], v1 = p[2 * i2 + 1][j];
            float h0 = __bfloat162float(__float2bfloat16(v0));
            float h1 = __bfloat162float(__float2bfloat16(v1));
            int c = tx * 4 + j;
            int w = c * Kp + (rbase + r) / 2;
            oh[w] = pk2(h0, h1);
            ol[w] = pk2(v0 - h0, v1 - h1);
        }
    }
}

// ---------------- bf16-split tensor-core GEMM ----------------
#define ASTR 20
#define BSTR 20

struct SmemTC {
    __align__(16) uint32_t Ah[128 * ASTR];
    __align__(16) uint32_t Al[128 * ASTR];
    __align__(16) uint32_t B[2][2][64 * BSTR];
};

__device__ __forceinline__ void gemm_bf_seg(
    const float* __restrict__ A, const uint32_t* __restrict__ Bh,
    const uint32_t* __restrict__ Bl, int M, int K,
    int bm, int bn, int tid, SmemTC* sm, float acc[2][4][4],
    bool doPrelu, float aA)
{
    const int lane = tid & 31, warp = tid >> 5;
    const int wm = warp & 3, wn = warp >> 2;
    const int g = lane >> 2, tq = lane & 3;
    const int Kp = K >> 1;
    const int nt = K / 32;

    float4 aS[4];

    auto stageA = [&](int t) {
        #pragma unroll
        for (int l = 0; l < 4; l++) {
            int idx = tid + l * 256;
            int r = idx >> 3, q = idx & 7;
            int row = bm + r;
            float4 v = make_float4(0.f, 0.f, 0.f, 0.f);
            if (row < M)
                v = *reinterpret_cast<const float4*>(&A[(size_t)row * K + t * 32 + q * 4]);
            aS[l] = v;
        }
    };
    auto storeA = [&]() {
        #pragma unroll
        for (int l = 0; l < 4; l++) {
            int idx = tid + l * 256;
            int r = idx >> 3, q = idx & 7;
            float4 v = aS[l];
            if (doPrelu) {
                v.x = (v.x >= 0.f) ? v.x : aA * v.x;
                v.y = (v.y >= 0.f) ? v.y : aA * v.y;
                v.z = (v.z >= 0.f) ? v.z : aA * v.z;
                v.w = (v.w >= 0.f) ? v.w : aA * v.w;
            }
            float hx = __bfloat162float(__float2bfloat16(v.x));
            float hy = __bfloat162float(__float2bfloat16(v.y));
            float hz = __bfloat162float(__float2bfloat16(v.z));
            float hw = __bfloat162float(__float2bfloat16(v.w));
            uint2 hp = make_uint2(pk2(hx, hy), pk2(hz, hw));
            uint2 lp = make_uint2(pk2(v.x - hx, v.y - hy), pk2(v.z - hz, v.w - hw));
            *reinterpret_cast<uint2*>(&sm->Ah[r * ASTR + q * 2]) = hp;
            *reinterpret_cast<uint2*>(&sm->Al[r * ASTR + q * 2]) = lp;
        }
    };
    auto cpB = [&](int t, int buf) {
        int n = tid >> 2;
        int c = (tid & 3) * 4;
        const uint32_t* sh = Bh + (size_t)(bn + n) * Kp + t * 16 + c;
        const uint32_t* sl = Bl + (size_t)(bn + n) * Kp + t * 16 + c;
        cp_async16(&sm->B[buf][0][n * BSTR + c], sh);
        cp_async16(&sm->B[buf][1][n * BSTR + c], sl);
        cp_async_commit();
    };

    stageA(0);
    cpB(0, 0);
    storeA();
    cp_async_wait0();
    __syncthreads();

    int buf = 0;
    for (int t = 0; t < nt; t++) {
        bool more = (t + 1 < nt);
        if (more) { stageA(t + 1); cpB(t + 1, buf ^ 1); }

        const uint32_t* aH = sm->Ah + (wm * 32 + g) * ASTR;
        const uint32_t* aL = sm->Al + (wm * 32 + g) * ASTR;
        const uint32_t* bH = sm->B[buf][0] + (wn * 32 + g) * BSTR;
        const uint32_t* bL = sm->B[buf][1] + (wn * 32 + g) * BSTR;

        #pragma unroll
        for (int kk = 0; kk < 2; kk++) {
            int kb = kk * 8;
            uint32_t ah[2][4], alr[2][4];
            #pragma unroll
            for (int im = 0; im < 2; im++) {
                const uint32_t* pH = aH + im * 16 * ASTR;
                const uint32_t* pL = aL + im * 16 * ASTR;
                ah[im][0] = pH[kb + tq];
                ah[im][1] = pH[8 * ASTR + kb + tq];
                ah[im][2] = pH[kb + tq + 4];
                ah[im][3] = pH[8 * ASTR + kb + tq + 4];
                alr[im][0] = pL[kb + tq];
                alr[im][1] = pL[8 * ASTR + kb + tq];
                alr[im][2] = pL[kb + tq + 4];
                alr[im][3] = pL[8 * ASTR + kb + tq + 4];
            }
            uint32_t bh[4][2], blr[4][2];
            #pragma unroll
            for (int jn = 0; jn < 4; jn++) {
                const uint32_t* qH = bH + jn * 8 * BSTR;
                const uint32_t* qL = bL + jn * 8 * BSTR;
                bh[jn][0] = qH[kb + tq];
                bh[jn][1] = qH[kb + tq + 4];
                blr[jn][0] = qL[kb + tq];
                blr[jn][1] = qL[kb + tq + 4];
            }
            #pragma unroll
            for (int im = 0; im < 2; im++)
                #pragma unroll
                for (int jn = 0; jn < 4; jn++) {
                    mma_bf16(acc[im][jn], alr[im][0], alr[im][1], alr[im][2], alr[im][3],
                             bh[jn][0], bh[jn][1]);
                    mma_bf16(acc[im][jn], ah[im][0], ah[im][1], ah[im][2], ah[im][3],
                             blr[jn][0], blr[jn][1]);
                    mma_bf16(acc[im][jn], ah[im][0], ah[im][1], ah[im][2], ah[im][3],
                             bh[jn][0], bh[jn][1]);
                }
        }
        __syncthreads();
        if (more) storeA();
        cp_async_wait0();
        __syncthreads();
        buf ^= 1;
    }
}

// HOUT=true -> D is __half* (fp16 output); false -> float*
template<bool HOUT>
__global__ void __launch_bounds__(256, 2)
gemm_bf_k(const float* __restrict__ A, const uint32_t* __restrict__ Bh,
          const uint32_t* __restrict__ Bl, int K,
          const float* __restrict__ A2, const uint32_t* __restrict__ B2h,
          const uint32_t* __restrict__ B2l, int K2,
          void* __restrict__ D, int M, int ldD,
          const float* __restrict__ preluA, const float* __restrict__ alphaOut)
{
    __shared__ SmemTC sm;
    const int tid = threadIdx.x;
    const int bm = blockIdx.y * 128, bn = blockIdx.x * 64;

    float acc[2][4][4] = {};
    const float aA = preluA ? preluA[0] : 0.f;

    gemm_bf_seg(A, Bh, Bl, M, K, bm, bn, tid, &sm, acc, preluA != nullptr, aA);
    if (A2)
        gemm_bf_seg(A2, B2h, B2l, M, K2, bm, bn, tid, &sm, acc, false, 0.f);

    const int lane = tid & 31, warp = tid >> 5;
    const int wm = warp & 3, wn = warp >> 2;
    const int g = lane >> 2, tq = lane & 3;
    const float al = alphaOut ? alphaOut[0] : 0.f;

    #pragma unroll
    for (int im = 0; im < 2; im++)
        #pragma unroll
        for (int jn = 0; jn < 4; jn++) {
            int r0 = bm + wm * 32 + im * 16 + g;
            int c0 = bn + wn * 32 + jn * 8 + 2 * tq;
            float2 v0 = make_float2(acc[im][jn][0], acc[im][jn][1]);
            float2 v1 = make_float2(acc[im][jn][2], acc[im][jn][3]);
            if (alphaOut) {
                v0.x = (v0.x >= 0.f) ? v0.x : al * v0.x;
                v0.y = (v0.y >= 0.f) ? v0.y : al * v0.y;
                v1.x = (v1.x >= 0.f) ? v1.x : al * v1.x;
                v1.y = (v1.y >= 0.f) ? v1.y : al * v1.y;
            }
            if (HOUT) {
                __half* Dh = (__half*)D;
                if (r0 < M)
                    *reinterpret_cast<__half2*>(&Dh[(size_t)r0 * ldD + c0]) = __floats2half2_rn(v0.x, v0.y);
                if (r0 + 8 < M)
                    *reinterpret_cast<__half2*>(&Dh[(size_t)(r0 + 8) * ldD + c0]) = __floats2half2_rn(v1.x, v1.y);
            } else {
                float* Df = (float*)D;
                if (r0 < M)     *reinterpret_cast<float2*>(&Df[(size_t)r0 * ldD + c0]) = v0;
                if (r0 + 8 < M) *reinterpret_cast<float2*>(&Df[(size_t)(r0 + 8) * ldD + c0]) = v1;
            }
        }
}

// ---------------- launch ----------------
extern "C" void kernel_launch(void* const* d_in, const int* in_sizes, int n_in,
                              void* d_out, int out_size)
{
    const float* seq  = (const float*)d_in[0];
    const int*   ei   = (const int*)  d_in[1];
    const float* ew   = (const float*)d_in[2];
    const float* W1   = (const float*)d_in[3];
    const float* b1   = (const float*)d_in[4];
    const float* W2   = (const float*)d_in[5];
    const float* b2   = (const float*)d_in[6];
    const float* a1   = (const float*)d_in[7];
    const float* a2   = (const float*)d_in[8];
    const float* a3   = (const float*)d_in[9];
    const float* Wfc1 = (const float*)d_in[10];
    const float* Wfc2 = (const float*)d_in[11];
    const float* Wfc3 = (const float*)d_in[12];
    const float* Wfc4 = (const float*)d_in[13];

    const int N = in_sizes[0] / INC;     // 50000
    const int E = in_sizes[2];           // 800000
    const int* src = ei;
    const int* dst = ei + E;

    __half *H1, *H2;
    float *A1, *ewS;
    int *off, *cnt, *srcS, *bsum;
    uint32_t *W1h, *W1l, *W2h, *W2l, *PAh, *PAl, *PBh, *PBl;
    cudaGetSymbolAddress((void**)&H1, g_H1);
    cudaGetSymbolAddress((void**)&A1, g_A1);
    cudaGetSymbolAddress((void**)&H2, g_H2);
    cudaGetSymbolAddress((void**)&off, g_off);
    cudaGetSymbolAddress((void**)&cnt, g_cnt);
    cudaGetSymbolAddress((void**)&srcS, g_srcS);
    cudaGetSymbolAddress((void**)&ewS, g_ewS);
    cudaGetSymbolAddress((void**)&bsum, g_bsum);
    cudaGetSymbolAddress((void**)&W1h, g_W1h);
    cudaGetSymbolAddress((void**)&W1l, g_W1l);
    cudaGetSymbolAddress((void**)&W2h, g_W2h);
    cudaGetSymbolAddress((void**)&W2l, g_W2l);
    cudaGetSymbolAddress((void**)&PAh, g_PAh);
    cudaGetSymbolAddress((void**)&PAl, g_PAl);
    cudaGetSymbolAddress((void**)&PBh, g_PBh);
    cudaGetSymbolAddress((void**)&PBl, g_PBl);

    float* outx = (float*)d_out;                      // x:     [N,128]
    float* outf = (float*)d_out + (size_t)N * HC;     // feat1: [N,64]

    const dim3 blk(256);
    const int gy = (N + 127) / 128;                   // 391
    const int nb = (N + 255) / 256;                   // 196

    // ---- CSR build (dst-sorted src/weight arrays) ----
    zero_cnt_k<<<nb, blk>>>(cnt, N);
    hist_k<<<(E + 255) / 256, blk>>>(dst, cnt, E);
    scan1_k<<<nb, blk>>>(cnt, off, bsum, N);
    scan2_k<<<1, blk>>>(bsum, nb);
    scan3_k<<<nb, blk>>>(off, bsum, cnt, N, E);
    fill_k<<<(E + 255) / 256, blk>>>(dst, src, ew, cnt, srcS, ewS, E);

    // ---- weight prep: combined splits + fused FC-head fold ----
    splitw2_k<<<(2*HC*INC/2 + HC*HC + 255) / 256, blk>>>(W1, W1h, W1l, W2, W2h, W2l);
    fold_k<<<6, blk>>>(Wfc1, Wfc2, Wfc3, Wfc4, PAh, PAl, PBh, PBl);

    // ---- GCN layer 1: H1 (fp16) = seq@W1; A1 = agg + b1 ----
    gemm_bf_k<true><<<dim3(4, gy), blk>>>(seq, W1h, W1l, INC,
                                          nullptr, nullptr, nullptr, 0,
                                          H1, N, 2*HC, nullptr, nullptr);
    agg_k<2*HC, false><<<(N + 7) / 8, blk>>>(H1, srcS, ewS, off, b1, nullptr, A1, N);

    // ---- GCN layer 2: H2 (fp16) = prelu(A1,a1)@W2; outx = prelu(agg + b2, a2) ----
    gemm_bf_k<true><<<dim3(2, gy), blk>>>(A1, W2h, W2l, 2*HC,
                                          nullptr, nullptr, nullptr, 0,
                                          H2, N, HC, a1, nullptr);
    agg_k<HC, true><<<(N + 7) / 8, blk>>>(H2, srcS, ewS, off, b2, a2, outx, N);

    // ---- fused head: feat1 = prelu(seq@PA + x@PB, a3) ----
    gemm_bf_k<false><<<dim3(1, gy), blk>>>(seq, PAh, PAl, INC,
                                           outx, PBh, PBl, HC,
                                           outf, N, OUTC, nullptr, a3);
}

// round 14
// speedup vs baseline: 5.4339x; 1.2873x over previous
#include <cuda_runtime.h>
#include <cuda_bf16.h>
#include <cuda_fp16.h>
#include <cstdint>

#define NNODES 50000
#define EMAX   800000
#define INC    256
#define HC     128
#define OUTC   64

// ---------------- scratch (static __device__ — no allocations) ----------------
__device__ __half g_H1[NNODES * 2 * HC];  // seq@W1 (fp16)     [N,256]
__device__ float  g_A1[NNODES * 2 * HC];  // agg1 (pre-act)    [N,256]
__device__ __half g_H2[NNODES * HC];      // prelu(A1)@W2 fp16 [N,128]

// CSR build state
__device__ int   g_off[NNODES + 1];
__device__ int   g_cnt[NNODES];
__device__ int2  g_eS[EMAX];              // dst-sorted packed {src, ew-bits}
__device__ int   g_bsum[256];

// packed bf16x2 weight splits: layout [n][K/2]
__device__ uint32_t g_W1h[2*HC * INC/2], g_W1l[2*HC * INC/2];
__device__ uint32_t g_W2h[HC * 2*HC/2],  g_W2l[HC * 2*HC/2];
__device__ uint32_t g_PAh[OUTC * INC/2], g_PAl[OUTC * INC/2];
__device__ uint32_t g_PBh[OUTC * HC/2],  g_PBl[OUTC * HC/2];

// ---------------- small helpers ----------------
__device__ __forceinline__ void cp_async16(void* smem_dst, const void* gmem_src) {
    uint32_t s = (uint32_t)__cvta_generic_to_shared(smem_dst);
    asm volatile("cp.async.cg.shared.global [%0], [%1], 16;\n" :: "r"(s), "l"(gmem_src));
}
__device__ __forceinline__ void cp_async_commit() {
    asm volatile("cp.async.commit_group;\n" ::: "memory");
}
__device__ __forceinline__ void cp_async_wait0() {
    asm volatile("cp.async.wait_group 0;\n" ::: "memory");
}
__device__ __forceinline__ uint32_t pk2(float e, float o) {   // e->low16, o->high16
    __nv_bfloat162 p = __floats2bfloat162_rn(e, o);
    return *reinterpret_cast<uint32_t*>(&p);
}
__device__ __forceinline__ void mma_bf16(float d[4],
    uint32_t a0, uint32_t a1, uint32_t a2, uint32_t a3, uint32_t b0, uint32_t b1)
{
    asm volatile(
        "mma.sync.aligned.m16n8k16.row.col.f32.bf16.bf16.f32 "
        "{%0,%1,%2,%3}, {%4,%5,%6,%7}, {%8,%9}, {%0,%1,%2,%3};\n"
        : "+f"(d[0]), "+f"(d[1]), "+f"(d[2]), "+f"(d[3])
        : "r"(a0), "r"(a1), "r"(a2), "r"(a3), "r"(b0), "r"(b1));
}

// ---------------- prep: weight splits + cnt zero (fused, independent work) ----------------
__device__ __forceinline__ void split_one(const float* __restrict__ W,
    uint32_t* __restrict__ hi, uint32_t* __restrict__ lo, int Kp, int N, int idx)
{
    int n = idx / Kp, kp = idx % Kp;
    float v0 = W[(size_t)(2 * kp) * N + n];
    float v1 = W[(size_t)(2 * kp + 1) * N + n];
    float h0 = __bfloat162float(__float2bfloat16(v0));
    float h1 = __bfloat162float(__float2bfloat16(v1));
    hi[idx] = pk2(h0, h1);
    lo[idx] = pk2(v0 - h0, v1 - h1);
}
__global__ void prep_k(const float* __restrict__ W1, uint32_t* __restrict__ W1h,
                       uint32_t* __restrict__ W1l,
                       const float* __restrict__ W2, uint32_t* __restrict__ W2h,
                       uint32_t* __restrict__ W2l,
                       int* __restrict__ cnt, int n)
{
    int idx = blockIdx.x * blockDim.x + threadIdx.x;
    const int n1 = 2*HC * INC/2;           // 32768
    const int n2 = HC * 2*HC/2;            // 16384
    if (idx < n) cnt[idx] = 0;
    if (idx < n1)            split_one(W1, W1h, W1l, INC/2, 2*HC, idx);
    else if (idx < n1 + n2)  split_one(W2, W2h, W2l, 2*HC/2, HC, idx - n1);
}

// ---------------- CSR build ----------------
__global__ void hist_k(const int* __restrict__ dst, int* __restrict__ cnt, int E) {
    int e = blockIdx.x * blockDim.x + threadIdx.x;
    if (e < E) atomicAdd(&cnt[dst[e]], 1);
}
__global__ void scan1_k(const int* __restrict__ cnt, int* __restrict__ off,
                        int* __restrict__ bsum, int n)
{
    __shared__ int s[256];
    int tid = threadIdx.x;
    int i = blockIdx.x * 256 + tid;
    int v = (i < n) ? cnt[i] : 0;
    s[tid] = v; __syncthreads();
    #pragma unroll
    for (int d = 1; d < 256; d <<= 1) {
        int t = (tid >= d) ? s[tid - d] : 0;
        __syncthreads();
        s[tid] += t;
        __syncthreads();
    }
    if (i < n) off[i] = s[tid] - v;        // exclusive within block
    if (tid == 255) bsum[blockIdx.x] = s[255];   // raw block totals
}
// scan3: each block computes sum(bsum[0..bid)) locally (nb <= 256), adds to its offsets.
__global__ void scan3_k(int* __restrict__ off, const int* __restrict__ bsum,
                        int* __restrict__ cnt, int n, int E, int nb)
{
    __shared__ int red[256];
    int tid = threadIdx.x;
    int v = (tid < nb && tid < (int)blockIdx.x) ? bsum[tid] : 0;
    red[tid] = v; __syncthreads();
    #pragma unroll
    for (int d = 128; d > 0; d >>= 1) {
        if (tid < d) red[tid] += red[tid + d];
        __syncthreads();
    }
    int base = red[0];
    int i = blockIdx.x * 256 + tid;
    if (i < n) {
        int o = off[i] + base;
        off[i] = o;
        cnt[i] = o;                        // fill cursor
    }
    if (blockIdx.x == 0 && tid == 0) off[n] = E;
}
__global__ void fill_k(const int* __restrict__ dst, const int* __restrict__ src,
                       const float* __restrict__ ew, int* __restrict__ cnt,
                       int2* __restrict__ eS, int E)
{
    int e = blockIdx.x * blockDim.x + threadIdx.x;
    if (e < E) {
        int p = atomicAdd(&cnt[dst[e]], 1);
        eS[p] = make_int2(src[e], __float_as_int(ew[e]));
    }
}

// ---------------- fp16 unpack-accumulate helpers ----------------
__device__ __forceinline__ void acc8(float* acc, uint4 v, float w) {
    float2 f;
    f = __half22float2(*reinterpret_cast<__half2*>(&v.x)); acc[0] += w * f.x; acc[1] += w * f.y;
    f = __half22float2(*reinterpret_cast<__half2*>(&v.y)); acc[2] += w * f.x; acc[3] += w * f.y;
    f = __half22float2(*reinterpret_cast<__half2*>(&v.z)); acc[4] += w * f.x; acc[5] += w * f.y;
    f = __half22float2(*reinterpret_cast<__half2*>(&v.w)); acc[6] += w * f.x; acc[7] += w * f.y;
}
__device__ __forceinline__ void acc4(float* acc, uint2 v, float w) {
    float2 f;
    f = __half22float2(*reinterpret_cast<__half2*>(&v.x)); acc[0] += w * f.x; acc[1] += w * f.y;
    f = __half22float2(*reinterpret_cast<__half2*>(&v.y)); acc[2] += w * f.x; acc[3] += w * f.y;
}

// ---------------- CSR aggregation over fp16 h: out = (bias + sum ew*h[src]) [prelu] ----------------
template<int C, bool PRELU>
__global__ void __launch_bounds__(256) agg_k(
    const __half* __restrict__ h, const int2* __restrict__ eS,
    const int* __restrict__ off,
    const float* __restrict__ bias, const float* __restrict__ alpha,
    float* __restrict__ out, int n)
{
    int node = blockIdx.x * 8 + (threadIdx.x >> 5);
    int lane = threadIdx.x & 31;
    if (node >= n) return;
    int s0 = __ldg(off + node), s1 = __ldg(off + node + 1);
    constexpr int F = C / 32;               // halves per lane: 8 (C=256) or 4 (C=128)
    float acc[F];
    #pragma unroll
    for (int j = 0; j < F; j += 4) {
        float4 b4 = *reinterpret_cast<const float4*>(&bias[lane * F + j]);
        acc[j] = b4.x; acc[j+1] = b4.y; acc[j+2] = b4.z; acc[j+3] = b4.w;
    }

    int e = s0;
    if constexpr (C == 256) {
        constexpr int RS = C / 8;           // uint4 (8 halves) per row = 32
        const uint4* hv = reinterpret_cast<const uint4*>(h);
        for (; e + 4 <= s1; e += 4) {
            int2 ep[4]; uint4 vv[4];
            #pragma unroll
            for (int q = 0; q < 4; q++) ep[q] = __ldg(eS + e + q);
            #pragma unroll
            for (int q = 0; q < 4; q++) vv[q] = __ldg(hv + (size_t)ep[q].x * RS + lane);
            #pragma unroll
            for (int q = 0; q < 4; q++) acc8(acc, vv[q], __int_as_float(ep[q].y));
        }
        for (; e < s1; e++) {
            int2 ep = __ldg(eS + e);
            acc8(acc, __ldg(hv + (size_t)ep.x * RS + lane), __int_as_float(ep.y));
        }
    } else {
        constexpr int RS = C / 4;           // uint2 (4 halves) per row = 32
        const uint2* hv = reinterpret_cast<const uint2*>(h);
        for (; e + 4 <= s1; e += 4) {
            int2 ep[4]; uint2 vv[4];
            #pragma unroll
            for (int q = 0; q < 4; q++) ep[q] = __ldg(eS + e + q);
            #pragma unroll
            for (int q = 0; q < 4; q++) vv[q] = __ldg(hv + (size_t)ep[q].x * RS + lane);
            #pragma unroll
            for (int q = 0; q < 4; q++) acc4(acc, vv[q], __int_as_float(ep[q].y));
        }
        for (; e < s1; e++) {
            int2 ep = __ldg(eS + e);
            acc4(acc, __ldg(hv + (size_t)ep.x * RS + lane), __int_as_float(ep.y));
        }
    }

    if (PRELU) {
        float al = alpha[0];
        #pragma unroll
        for (int j = 0; j < F; j++)
            acc[j] = (acc[j] >= 0.f) ? acc[j] : al * acc[j];
    }
    #pragma unroll
    for (int j = 0; j < F; j += 4)
        *reinterpret_cast<float4*>(&out[(size_t)node * C + lane * F + j]) =
            make_float4(acc[j], acc[j+1], acc[j+2], acc[j+3]);
}

// ---------------- fused fold: PA = Wfc2@Wfc3top@Wfc4, PB = Wfc1@Wfc3bot@Wfc4 ----------------
__global__ void __launch_bounds__(256) fold_k(
    const float* __restrict__ Wfc1, const float* __restrict__ Wfc2,
    const float* __restrict__ Wfc3, const float* __restrict__ Wfc4,
    uint32_t* __restrict__ PAh, uint32_t* __restrict__ PAl,
    uint32_t* __restrict__ PBh, uint32_t* __restrict__ PBl)
{
    __shared__ float As[16][64];
    __shared__ float Bs[16][128];
    __shared__ float Ts[64][132];

    int b = blockIdx.x;
    const float* X; const float* W3p; uint32_t *oh, *ol; int Kp, rbase;
    if (b < 4) { X = Wfc2 + b * 64 * 256;       W3p = Wfc3;             oh = PAh; ol = PAl; Kp = 128; rbase = b * 64; }
    else       { X = Wfc1 + (b - 4) * 64 * 256; W3p = Wfc3 + 256 * 128; oh = PBh; ol = PBl; Kp = 64;  rbase = (b - 4) * 64; }

    int tid = threadIdx.x, tx = tid & 15, ty = tid >> 4;

    float acc[4][8] = {};
    for (int k0 = 0; k0 < 256; k0 += 16) {
        { int r = tid >> 2, kc = (tid & 3) * 4;
          float4 v = *reinterpret_cast<const float4*>(&X[r * 256 + k0 + kc]);
          As[kc + 0][r] = v.x; As[kc + 1][r] = v.y; As[kc + 2][r] = v.z; As[kc + 3][r] = v.w; }
        #pragma unroll
        for (int l = 0; l < 2; l++) {
            int idx = tid + l * 256;
            int kk = idx >> 5, c = (idx & 31) * 4;
            *reinterpret_cast<float4*>(&Bs[kk][c]) =
                *reinterpret_cast<const float4*>(&W3p[(k0 + kk) * 128 + c]);
        }
        __syncthreads();
        #pragma unroll
        for (int kk = 0; kk < 16; kk++) {
            float a[4], bb[8];
            #pragma unroll
            for (int i = 0; i < 4; i++) a[i] = As[kk][ty * 4 + i];
            #pragma unroll
            for (int j = 0; j < 8; j++) bb[j] = Bs[kk][tx * 8 + j];
            #pragma unroll
            for (int i = 0; i < 4; i++)
                #pragma unroll
                for (int j = 0; j < 8; j++)
                    acc[i][j] += a[i] * bb[j];
        }
        __syncthreads();
    }
    #pragma unroll
    for (int i = 0; i < 4; i++)
        #pragma unroll
        for (int j = 0; j < 8; j++)
            Ts[ty * 4 + i][tx * 8 + j] = acc[i][j];
    __syncthreads();

    float p[4][4] = {};
    for (int k = 0; k < 128; k++) {
        float4 bb = *reinterpret_cast<const float4*>(&Wfc4[k * 64 + tx * 4]);
        float a0 = Ts[ty * 4 + 0][k], a1 = Ts[ty * 4 + 1][k];
        float a2 = Ts[ty * 4 + 2][k], a3 = Ts[ty * 4 + 3][k];
        p[0][0] += a0 * bb.x; p[0][1] += a0 * bb.y; p[0][2] += a0 * bb.z; p[0][3] += a0 * bb.w;
        p[1][0] += a1 * bb.x; p[1][1] += a1 * bb.y; p[1][2] += a1 * bb.z; p[1][3] += a1 * bb.w;
        p[2][0] += a2 * bb.x; p[2][1] += a2 * bb.y; p[2][2] += a2 * bb.z; p[2][3] += a2 * bb.w;
        p[3][0] += a3 * bb.x; p[3][1] += a3 * bb.y; p[3][2] += a3 * bb.z; p[3][3] += a3 * bb.w;
    }

    #pragma unroll
    for (int i2 = 0; i2 < 2; i2++) {
        int r = ty * 4 + 2 * i2;
        #pragma unroll
        for (int j = 0; j < 4; j++) {
            float v0 = p[2 * i2][j], v1 = p[2 * i2 + 1][j];
            float h0 = __bfloat162float(__float2bfloat16(v0));
            float h1 = __bfloat162float(__float2bfloat16(v1));
            int c = tx * 4 + j;
            int w = c * Kp + (rbase + r) / 2;
            oh[w] = pk2(h0, h1);
            ol[w] = pk2(v0 - h0, v1 - h1);
        }
    }
}

// ---------------- bf16-split tensor-core GEMM ----------------
#define ASTR 20
#define BSTR 20

struct SmemTC {
    __align__(16) uint32_t Ah[128 * ASTR];
    __align__(16) uint32_t Al[128 * ASTR];
    __align__(16) uint32_t B[2][2][64 * BSTR];
};

__device__ __forceinline__ void gemm_bf_seg(
    const float* __restrict__ A, const uint32_t* __restrict__ Bh,
    const uint32_t* __restrict__ Bl, int M, int K,
    int bm, int bn, int tid, SmemTC* sm, float acc[2][4][4],
    bool doPrelu, float aA)
{
    const int lane = tid & 31, warp = tid >> 5;
    const int wm = warp & 3, wn = warp >> 2;
    const int g = lane >> 2, tq = lane & 3;
    const int Kp = K >> 1;
    const int nt = K / 32;

    float4 aS[4];

    auto stageA = [&](int t) {
        #pragma unroll
        for (int l = 0; l < 4; l++) {
            int idx = tid + l * 256;
            int r = idx >> 3, q = idx & 7;
            int row = bm + r;
            float4 v = make_float4(0.f, 0.f, 0.f, 0.f);
            if (row < M)
                v = *reinterpret_cast<const float4*>(&A[(size_t)row * K + t * 32 + q * 4]);
            aS[l] = v;
        }
    };
    auto storeA = [&]() {
        #pragma unroll
        for (int l = 0; l < 4; l++) {
            int idx = tid + l * 256;
            int r = idx >> 3, q = idx & 7;
            float4 v = aS[l];
            if (doPrelu) {
                v.x = (v.x >= 0.f) ? v.x : aA * v.x;
                v.y = (v.y >= 0.f) ? v.y : aA * v.y;
                v.z = (v.z >= 0.f) ? v.z : aA * v.z;
                v.w = (v.w >= 0.f) ? v.w : aA * v.w;
            }
            float hx = __bfloat162float(__float2bfloat16(v.x));
            float hy = __bfloat162float(__float2bfloat16(v.y));
            float hz = __bfloat162float(__float2bfloat16(v.z));
            float hw = __bfloat162float(__float2bfloat16(v.w));
            uint2 hp = make_uint2(pk2(hx, hy), pk2(hz, hw));
            uint2 lp = make_uint2(pk2(v.x - hx, v.y - hy), pk2(v.z - hz, v.w - hw));
            *reinterpret_cast<uint2*>(&sm->Ah[r * ASTR + q * 2]) = hp;
            *reinterpret_cast<uint2*>(&sm->Al[r * ASTR + q * 2]) = lp;
        }
    };
    auto cpB = [&](int t, int buf) {
        int n = tid >> 2;
        int c = (tid & 3) * 4;
        const uint32_t* sh = Bh + (size_t)(bn + n) * Kp + t * 16 + c;
        const uint32_t* sl = Bl + (size_t)(bn + n) * Kp + t * 16 + c;
        cp_async16(&sm->B[buf][0][n * BSTR + c], sh);
        cp_async16(&sm->B[buf][1][n * BSTR + c], sl);
        cp_async_commit();
    };

    stageA(0);
    cpB(0, 0);
    storeA();
    cp_async_wait0();
    __syncthreads();

    int buf = 0;
    for (int t = 0; t < nt; t++) {
        bool more = (t + 1 < nt);
        if (more) { stageA(t + 1); cpB(t + 1, buf ^ 1); }

        const uint32_t* aH = sm->Ah + (wm * 32 + g) * ASTR;
        const uint32_t* aL = sm->Al + (wm * 32 + g) * ASTR;
        const uint32_t* bH = sm->B[buf][0] + (wn * 32 + g) * BSTR;
        const uint32_t* bL = sm->B[buf][1] + (wn * 32 + g) * BSTR;

        #pragma unroll
        for (int kk = 0; kk < 2; kk++) {
            int kb = kk * 8;
            uint32_t ah[2][4], alr[2][4];
            #pragma unroll
            for (int im = 0; im < 2; im++) {
                const uint32_t* pH = aH + im * 16 * ASTR;
                const uint32_t* pL = aL + im * 16 * ASTR;
                ah[im][0] = pH[kb + tq];
                ah[im][1] = pH[8 * ASTR + kb + tq];
                ah[im][2] = pH[kb + tq + 4];
                ah[im][3] = pH[8 * ASTR + kb + tq + 4];
                alr[im][0] = pL[kb + tq];
                alr[im][1] = pL[8 * ASTR + kb + tq];
                alr[im][2] = pL[kb + tq + 4];
                alr[im][3] = pL[8 * ASTR + kb + tq + 4];
            }
            uint32_t bh[4][2], blr[4][2];
            #pragma unroll
            for (int jn = 0; jn < 4; jn++) {
                const uint32_t* qH = bH + jn * 8 * BSTR;
                const uint32_t* qL = bL + jn * 8 * BSTR;
                bh[jn][0] = qH[kb + tq];
                bh[jn][1] = qH[kb + tq + 4];
                blr[jn][0] = qL[kb + tq];
                blr[jn][1] = qL[kb + tq + 4];
            }
            #pragma unroll
            for (int im = 0; im < 2; im++)
                #pragma unroll
                for (int jn = 0; jn < 4; jn++) {
                    mma_bf16(acc[im][jn], alr[im][0], alr[im][1], alr[im][2], alr[im][3],
                             bh[jn][0], bh[jn][1]);
                    mma_bf16(acc[im][jn], ah[im][0], ah[im][1], ah[im][2], ah[im][3],
                             blr[jn][0], blr[jn][1]);
                    mma_bf16(acc[im][jn], ah[im][0], ah[im][1], ah[im][2], ah[im][3],
                             bh[jn][0], bh[jn][1]);
                }
        }
        __syncthreads();
        if (more) storeA();
        cp_async_wait0();
        __syncthreads();
        buf ^= 1;
    }
}

// HOUT=true -> D is __half* (fp16 output); false -> float*
template<bool HOUT>
__global__ void __launch_bounds__(256, 2)
gemm_bf_k(const float* __restrict__ A, const uint32_t* __restrict__ Bh,
          const uint32_t* __restrict__ Bl, int K,
          const float* __restrict__ A2, const uint32_t* __restrict__ B2h,
          const uint32_t* __restrict__ B2l, int K2,
          void* __restrict__ D, int M, int ldD,
          const float* __restrict__ preluA, const float* __restrict__ alphaOut)
{
    __shared__ SmemTC sm;
    const int tid = threadIdx.x;
    const int bm = blockIdx.y * 128, bn = blockIdx.x * 64;

    float acc[2][4][4] = {};
    const float aA = preluA ? preluA[0] : 0.f;

    gemm_bf_seg(A, Bh, Bl, M, K, bm, bn, tid, &sm, acc, preluA != nullptr, aA);
    if (A2)
        gemm_bf_seg(A2, B2h, B2l, M, K2, bm, bn, tid, &sm, acc, false, 0.f);

    const int lane = tid & 31, warp = tid >> 5;
    const int wm = warp & 3, wn = warp >> 2;
    const int g = lane >> 2, tq = lane & 3;
    const float al = alphaOut ? alphaOut[0] : 0.f;

    #pragma unroll
    for (int im = 0; im < 2; im++)
        #pragma unroll
        for (int jn = 0; jn < 4; jn++) {
            int r0 = bm + wm * 32 + im * 16 + g;
            int c0 = bn + wn * 32 + jn * 8 + 2 * tq;
            float2 v0 = make_float2(acc[im][jn][0], acc[im][jn][1]);
            float2 v1 = make_float2(acc[im][jn][2], acc[im][jn][3]);
            if (alphaOut) {
                v0.x = (v0.x >= 0.f) ? v0.x : al * v0.x;
                v0.y = (v0.y >= 0.f) ? v0.y : al * v0.y;
                v1.x = (v1.x >= 0.f) ? v1.x : al * v1.x;
                v1.y = (v1.y >= 0.f) ? v1.y : al * v1.y;
            }
            if (HOUT) {
                __half* Dh = (__half*)D;
                if (r0 < M)
                    *reinterpret_cast<__half2*>(&Dh[(size_t)r0 * ldD + c0]) = __floats2half2_rn(v0.x, v0.y);
                if (r0 + 8 < M)
                    *reinterpret_cast<__half2*>(&Dh[(size_t)(r0 + 8) * ldD + c0]) = __floats2half2_rn(v1.x, v1.y);
            } else {
                float* Df = (float*)D;
                if (r0 < M)     *reinterpret_cast<float2*>(&Df[(size_t)r0 * ldD + c0]) = v0;
                if (r0 + 8 < M) *reinterpret_cast<float2*>(&Df[(size_t)(r0 + 8) * ldD + c0]) = v1;
            }
        }
}

// ---------------- launch ----------------
extern "C" void kernel_launch(void* const* d_in, const int* in_sizes, int n_in,
                              void* d_out, int out_size)
{
    const float* seq  = (const float*)d_in[0];
    const int*   ei   = (const int*)  d_in[1];
    const float* ew   = (const float*)d_in[2];
    const float* W1   = (const float*)d_in[3];
    const float* b1   = (const float*)d_in[4];
    const float* W2   = (const float*)d_in[5];
    const float* b2   = (const float*)d_in[6];
    const float* a1   = (const float*)d_in[7];
    const float* a2   = (const float*)d_in[8];
    const float* a3   = (const float*)d_in[9];
    const float* Wfc1 = (const float*)d_in[10];
    const float* Wfc2 = (const float*)d_in[11];
    const float* Wfc3 = (const float*)d_in[12];
    const float* Wfc4 = (const float*)d_in[13];

    const int N = in_sizes[0] / INC;     // 50000
    const int E = in_sizes[2];           // 800000
    const int* src = ei;
    const int* dst = ei + E;

    __half *H1, *H2;
    float *A1;
    int *off, *cnt, *bsum;
    int2 *eS;
    uint32_t *W1h, *W1l, *W2h, *W2l, *PAh, *PAl, *PBh, *PBl;
    cudaGetSymbolAddress((void**)&H1, g_H1);
    cudaGetSymbolAddress((void**)&A1, g_A1);
    cudaGetSymbolAddress((void**)&H2, g_H2);
    cudaGetSymbolAddress((void**)&off, g_off);
    cudaGetSymbolAddress((void**)&cnt, g_cnt);
    cudaGetSymbolAddress((void**)&eS, g_eS);
    cudaGetSymbolAddress((void**)&bsum, g_bsum);
    cudaGetSymbolAddress((void**)&W1h, g_W1h);
    cudaGetSymbolAddress((void**)&W1l, g_W1l);
    cudaGetSymbolAddress((void**)&W2h, g_W2h);
    cudaGetSymbolAddress((void**)&W2l, g_W2l);
    cudaGetSymbolAddress((void**)&PAh, g_PAh);
    cudaGetSymbolAddress((void**)&PAl, g_PAl);
    cudaGetSymbolAddress((void**)&PBh, g_PBh);
    cudaGetSymbolAddress((void**)&PBl, g_PBl);

    float* outx = (float*)d_out;                      // x:     [N,128]
    float* outf = (float*)d_out + (size_t)N * HC;     // feat1: [N,64]

    const dim3 blk(256);
    const int gy = (N + 127) / 128;                   // 391
    const int nb = (N + 255) / 256;                   // 196

    // one-time side streams/events for fork-join capture (constant infra, no device mem)
    static cudaStream_t sB = nullptr, sC = nullptr;
    static cudaEvent_t evRoot = nullptr, evB = nullptr, evC = nullptr;
    if (sB == nullptr) {
        cudaStreamCreateWithFlags(&sB, cudaStreamNonBlocking);
        cudaStreamCreateWithFlags(&sC, cudaStreamNonBlocking);
        cudaEventCreateWithFlags(&evRoot, cudaEventDisableTiming);
        cudaEventCreateWithFlags(&evB, cudaEventDisableTiming);
        cudaEventCreateWithFlags(&evC, cudaEventDisableTiming);
    }

    // ---- root: weight splits + cnt zero on the capture stream ----
    prep_k<<<(N + 255) / 256, blk>>>(W1, W1h, W1l, W2, W2h, W2l, cnt, N);
    cudaEventRecord(evRoot, 0);
    cudaStreamWaitEvent(sB, evRoot, 0);
    cudaStreamWaitEvent(sC, evRoot, 0);

    // ---- stream B: CSR build ----
    hist_k<<<(E + 255) / 256, blk, 0, sB>>>(dst, cnt, E);
    scan1_k<<<nb, blk, 0, sB>>>(cnt, off, bsum, N);
    scan3_k<<<nb, blk, 0, sB>>>(off, bsum, cnt, N, E, nb);
    fill_k<<<(E + 255) / 256, blk, 0, sB>>>(dst, src, ew, cnt, eS, E);
    cudaEventRecord(evB, sB);

    // ---- stream C: head fold ----
    fold_k<<<6, blk, 0, sC>>>(Wfc1, Wfc2, Wfc3, Wfc4, PAh, PAl, PBh, PBl);
    cudaEventRecord(evC, sC);

    // ---- capture stream: GEMM1 overlaps CSR+fold ----
    gemm_bf_k<true><<<dim3(4, gy), blk>>>(seq, W1h, W1l, INC,
                                          nullptr, nullptr, nullptr, 0,
                                          H1, N, 2*HC, nullptr, nullptr);
    cudaStreamWaitEvent(0, evB, 0);
    agg_k<2*HC, false><<<(N + 7) / 8, blk>>>(H1, eS, off, b1, nullptr, A1, N);

    gemm_bf_k<true><<<dim3(2, gy), blk>>>(A1, W2h, W2l, 2*HC,
                                          nullptr, nullptr, nullptr, 0,
                                          H2, N, HC, a1, nullptr);
    agg_k<HC, true><<<(N + 7) / 8, blk>>>(H2, eS, off, b2, a2, outx, N);

    cudaStreamWaitEvent(0, evC, 0);
    gemm_bf_k<false><<<dim3(1, gy), blk>>>(seq, PAh, PAl, INC,
                                           outx, PBh, PBl, HC,
                                           outf, N, OUTC, nullptr, a3);
}